// round 6
// baseline (speedup 1.0000x reference)
#include <cuda_runtime.h>
#include <cuda_bf16.h>
#include <math.h>
#include <stdint.h>

#define BQ 4
#define PP 1024
#define DDA 1024
#define DDC 3072
#define HID 512
typedef __nv_bfloat16 bf16;

// ---------------- scratch (static device memory, no allocation) ----------------
__device__ float g_acos[(size_t)BQ*PP*PP];
__device__ float g_ccos[(size_t)BQ*PP*PP];
__device__ float g_na[BQ*PP];
__device__ float g_nc[BQ*PP];
__device__ bf16 g_ah[(size_t)BQ*PP*DDA], g_al[(size_t)BQ*PP*DDA];
__device__ bf16 g_ch[(size_t)BQ*PP*DDC], g_cl[(size_t)BQ*PP*DDC];
__device__ bf16 g_aadjh[(size_t)BQ*PP*PP], g_aadjl[(size_t)BQ*PP*PP];
__device__ bf16 g_cadjh[(size_t)BQ*PP*PP], g_cadjl[(size_t)BQ*PP*PP];
__device__ bf16 g_w1ah[DDA*HID], g_w1al[DDA*HID];
__device__ bf16 g_w2ah[HID*DDA], g_w2al[HID*DDA];
__device__ bf16 g_w1ch[DDC*HID], g_w1cl[DDC*HID];
__device__ bf16 g_w2ch[HID*DDC], g_w2cl[HID*DDC];
__device__ bf16 g_t1h[(size_t)BQ*PP*HID], g_t1l[(size_t)BQ*PP*HID];
__device__ bf16 g_t2h[(size_t)BQ*PP*HID], g_t2l[(size_t)BQ*PP*HID];
__device__ bf16 g_t3h[(size_t)BQ*PP*DDC], g_t3l[(size_t)BQ*PP*DDC];
__device__ bf16 g_ofah[(size_t)BQ*PP*DDA], g_ofal[(size_t)BQ*PP*DDA];
__device__ bf16 g_ofch[(size_t)BQ*PP*DDC], g_ofcl[(size_t)BQ*PP*DDC];
__device__ bf16 g_wp1h[DDA*128], g_wp1l[DDA*128];
__device__ bf16 g_wp2h[DDC*128], g_wp2l[DDC*128];
__device__ float g_hp1[(size_t)2*BQ*PP*128];
__device__ float g_hp2[(size_t)4*BQ*PP*128];

// ====================== low-level helpers ======================
__device__ __forceinline__ uint32_t smem_u32(const void* p) {
    uint32_t a;
    asm("{ .reg .u64 t; cvta.to.shared.u64 t, %1; cvt.u32.u64 %0, t; }" : "=r"(a) : "l"(p));
    return a;
}
__device__ __forceinline__ uint32_t pack_bf16x2(float lo_e, float hi_e) {
    uint32_t r;
    asm("cvt.rn.bf16x2.f32 %0, %1, %2;" : "=r"(r) : "f"(hi_e), "f"(lo_e));
    return r;
}
__device__ __forceinline__ void split2(float x, float y, uint32_t& h, uint32_t& l) {
    uint32_t ux = __float_as_uint(x), uy = __float_as_uint(y);
    h = __byte_perm(ux, uy, 0x7632);
    float lx = x - __uint_as_float(ux & 0xFFFF0000u);
    float ly = y - __uint_as_float(uy & 0xFFFF0000u);
    l = pack_bf16x2(lx, ly);
}
__device__ __forceinline__ void ldmx4(uint32_t* r, uint32_t addr) {
    asm volatile("ldmatrix.sync.aligned.m8n8.x4.shared.b16 {%0,%1,%2,%3}, [%4];"
                 : "=r"(r[0]), "=r"(r[1]), "=r"(r[2]), "=r"(r[3]) : "r"(addr));
}
__device__ __forceinline__ void ldmx4t(uint32_t* r, uint32_t addr) {
    asm volatile("ldmatrix.sync.aligned.m8n8.x4.trans.shared.b16 {%0,%1,%2,%3}, [%4];"
                 : "=r"(r[0]), "=r"(r[1]), "=r"(r[2]), "=r"(r[3]) : "r"(addr));
}
__device__ __forceinline__ void mma_bf16(float* c, const uint32_t* a, const uint32_t* b) {
    asm volatile(
        "mma.sync.aligned.m16n8k16.row.col.f32.bf16.bf16.f32 "
        "{%0,%1,%2,%3}, {%4,%5,%6,%7}, {%8,%9}, {%0,%1,%2,%3};"
        : "+f"(c[0]), "+f"(c[1]), "+f"(c[2]), "+f"(c[3])
        : "r"(a[0]), "r"(a[1]), "r"(a[2]), "r"(a[3]), "r"(b[0]), "r"(b[1]));
}
__device__ __forceinline__ void cp16(uint32_t dst, const void* src) {
    asm volatile("cp.async.cg.shared.global [%0], [%1], 16;" :: "r"(dst), "l"(src) : "memory");
}
#define CP_COMMIT() asm volatile("cp.async.commit_group;" ::: "memory")
#define CP_WAIT3()  asm volatile("cp.async.wait_group 3;" ::: "memory")

// ====================== bf16x3 multistage mma GEMM (512 threads) ==============
// C = A @ B (+bias, +resid, relu). A: hi/lo [M,K] bf16 row-major.
// TBK=1: B hi/lo [N,K]. TBK=0: B hi/lo [K,N].
// symm: skip blocks bx<by. Klen>0: K-split head mode (partial out, no epi-fuse).
#define AROWB 80
#define ATILE 10240
#define ASTG  20480
#define BSTG1 20480
#define BSTG0 16384
#define NSTAGE 5

template<int TBK>
__global__ __launch_bounds__(512, 1)
void gemmx_k(const bf16* __restrict__ Ah, const bf16* __restrict__ Al,
             const bf16* __restrict__ Bh, const bf16* __restrict__ Bl,
             float* __restrict__ C, bf16* __restrict__ Ch, bf16* __restrict__ Cl,
             int N, int K, int Klen, int symm,
             long sA, long sB, long sC,
             const float* __restrict__ bias,
             const float* __restrict__ resid, long sR,
             int ldc, int relu_flag)
{
    if (!Klen && symm && blockIdx.x < blockIdx.y) return;
    constexpr int BSTG = TBK ? BSTG1 : BSTG0;
    constexpr int SB = ASTG + BSTG;
    extern __shared__ char sm[];
    uint32_t smb = smem_u32(sm);

    const int tid = threadIdx.x;
    const int lane = tid & 31;
    const int wid = tid >> 5;          // 0..15
    const int wm = (wid >> 2) * 32;    // 4 M-warps
    const int wn = (wid & 3) * 32;     // 4 N-warps

    long bz = blockIdx.z;
    const int bm = blockIdx.y * 128;
    const int bn = Klen ? 0 : blockIdx.x * 128;
    const int kbase = Klen ? blockIdx.x * Klen : 0;
    const int KL = Klen ? Klen : K;

    const bf16* Ahb = Ah + bz * sA + (size_t)bm * K + kbase;
    const bf16* Alb = Al + bz * sA + (size_t)bm * K + kbase;
    const bf16* Bhb = TBK ? (Bh + bz * sB + (size_t)bn * K + kbase)
                          : (Bh + bz * sB + (size_t)kbase * N + bn);
    const bf16* Blb = TBK ? (Bl + bz * sB + (size_t)bn * K + kbase)
                          : (Bl + bz * sB + (size_t)kbase * N + bn);
    float* Cb = C ? (Klen ? C + (size_t)blockIdx.x * sC : C + bz * sC) : (float*)0;
    bf16* Chb = Ch ? Ch + bz * sC : (bf16*)0;
    bf16* Clb = Cl ? Cl + bz * sC : (bf16*)0;
    const float* Rb = resid ? resid + bz * sR : (const float*)0;

    float acc[2][4][4];
#pragma unroll
    for (int i = 0; i < 2; i++)
#pragma unroll
        for (int j = 0; j < 4; j++)
#pragma unroll
            for (int r = 0; r < 4; r++) acc[i][j][r] = 0.f;

    const int nch = KL >> 5;

    auto load_stage = [&](int kt, int s) {
        uint32_t base = smb + (uint32_t)s * SB;
        int k0 = kt << 5;
        int row = tid >> 2, c4 = tid & 3;
        // A hi/lo: 128 rows x 32 k
        cp16(base + row * AROWB + c4 * 16,
             Ahb + (size_t)row * K + k0 + c4 * 8);
        cp16(base + ATILE + row * AROWB + c4 * 16,
             Alb + (size_t)row * K + k0 + c4 * 8);
        if (TBK) {
            cp16(base + ASTG + row * AROWB + c4 * 16,
                 Bhb + (size_t)row * K + k0 + c4 * 8);
            cp16(base + ASTG + ATILE + row * AROWB + c4 * 16,
                 Blb + (size_t)row * K + k0 + c4 * 8);
        } else {
            int k = tid >> 4, c = tid & 15;
            uint32_t dst = base + ASTG + k * 256 + ((c ^ (k & 7)) << 4);
            cp16(dst, Bhb + (size_t)(k0 + k) * N + c * 8);
            cp16(dst + 8192, Blb + (size_t)(k0 + k) * N + c * 8);
        }
        CP_COMMIT();
    };

    load_stage(0, 0);
    load_stage(1, 1);
    load_stage(2, 2);
    load_stage(3, 3);

    int sc = 0, sl = 4;
    for (int kt = 0; kt < nch; kt++) {
        CP_WAIT3();
        __syncthreads();
        if (kt + 4 < nch) {
            load_stage(kt + 4, sl);
            sl = (sl == NSTAGE - 1) ? 0 : sl + 1;
        }
        uint32_t aB = smb + (uint32_t)sc * SB;
        uint32_t bB = aB + ASTG;
        sc = (sc == NSTAGE - 1) ? 0 : sc + 1;

#pragma unroll
        for (int kh = 0; kh < 2; kh++) {
            uint32_t ahi[2][4], alo[2][4], bhi[4][2], blo[4][2];
            {
                int arow = wm + (lane & 15);
                uint32_t aoff = (uint32_t)(kh * 32 + ((lane >> 4) << 4));
#pragma unroll
                for (int i = 0; i < 2; i++) {
                    uint32_t ro = (uint32_t)(arow + i * 16) * AROWB + aoff;
                    ldmx4(ahi[i], aB + ro);
                    ldmx4(alo[i], aB + ATILE + ro);
                }
            }
            if (TBK) {
                uint32_t boff = (uint32_t)(kh * 32 + (((lane >> 3) & 1) << 4));
#pragma unroll
                for (int jp = 0; jp < 2; jp++) {
                    int row = wn + jp * 16 + ((lane >> 4) << 3) + (lane & 7);
                    uint32_t ro = (uint32_t)row * AROWB + boff;
                    uint32_t rh[4], rl[4];
                    ldmx4(rh, bB + ro);
                    ldmx4(rl, bB + ATILE + ro);
                    bhi[2*jp][0] = rh[0]; bhi[2*jp][1] = rh[1];
                    bhi[2*jp+1][0] = rh[2]; bhi[2*jp+1][1] = rh[3];
                    blo[2*jp][0] = rl[0]; blo[2*jp][1] = rl[1];
                    blo[2*jp+1][0] = rl[2]; blo[2*jp+1][1] = rl[3];
                }
            } else {
                int cbase = wn >> 3;
                int k = kh * 16 + ((lane >> 3) & 1) * 8 + (lane & 7);
                uint32_t kro = (uint32_t)k << 8;
#pragma unroll
                for (int jp = 0; jp < 2; jp++) {
                    int colblk = cbase + 2 * jp + (lane >> 4);
                    uint32_t ad = kro + ((uint32_t)(colblk ^ (k & 7)) << 4);
                    uint32_t rh[4], rl[4];
                    ldmx4t(rh, bB + ad);
                    ldmx4t(rl, bB + 8192 + ad);
                    bhi[2*jp][0] = rh[0]; bhi[2*jp][1] = rh[1];
                    bhi[2*jp+1][0] = rh[2]; bhi[2*jp+1][1] = rh[3];
                    blo[2*jp][0] = rl[0]; blo[2*jp][1] = rl[1];
                    blo[2*jp+1][0] = rl[2]; blo[2*jp+1][1] = rl[3];
                }
            }
#pragma unroll
            for (int i = 0; i < 2; i++)
#pragma unroll
                for (int j = 0; j < 4; j++)
                    mma_bf16(acc[i][j], ahi[i], bhi[j]);
#pragma unroll
            for (int i = 0; i < 2; i++)
#pragma unroll
                for (int j = 0; j < 4; j++)
                    mma_bf16(acc[i][j], ahi[i], blo[j]);
#pragma unroll
            for (int i = 0; i < 2; i++)
#pragma unroll
                for (int j = 0; j < 4; j++)
                    mma_bf16(acc[i][j], alo[i], bhi[j]);
        }
    }

    // ---- epilogue ----
#pragma unroll
    for (int i = 0; i < 2; i++) {
        int r0 = bm + wm + i * 16 + (lane >> 2);
        int r1 = r0 + 8;
#pragma unroll
        for (int j = 0; j < 4; j++) {
            int gc = bn + wn + j * 8 + (lane & 3) * 2;
            float2 v0 = make_float2(acc[i][j][0], acc[i][j][1]);
            float2 v1 = make_float2(acc[i][j][2], acc[i][j][3]);
            if (bias) {
                float2 bv = *reinterpret_cast<const float2*>(bias + gc);
                v0.x += bv.x; v0.y += bv.y;
                v1.x += bv.x; v1.y += bv.y;
            }
            if (Rb) {
                float2 q0 = *reinterpret_cast<const float2*>(Rb + (size_t)r0 * ldc + gc);
                float2 q1 = *reinterpret_cast<const float2*>(Rb + (size_t)r1 * ldc + gc);
                v0.x += q0.x; v0.y += q0.y;
                v1.x += q1.x; v1.y += q1.y;
            }
            if (relu_flag) {
                v0.x = fmaxf(v0.x, 0.f); v0.y = fmaxf(v0.y, 0.f);
                v1.x = fmaxf(v1.x, 0.f); v1.y = fmaxf(v1.y, 0.f);
            }
            if (Cb) {
                *reinterpret_cast<float2*>(Cb + (size_t)r0 * ldc + gc) = v0;
                *reinterpret_cast<float2*>(Cb + (size_t)r1 * ldc + gc) = v1;
            }
            if (Chb) {
                uint32_t h0, l0, h1, l1;
                split2(v0.x, v0.y, h0, l0);
                split2(v1.x, v1.y, h1, l1);
                *reinterpret_cast<uint32_t*>(Chb + (size_t)r0 * ldc + gc) = h0;
                *reinterpret_cast<uint32_t*>(Clb + (size_t)r0 * ldc + gc) = l0;
                *reinterpret_cast<uint32_t*>(Chb + (size_t)r1 * ldc + gc) = h1;
                *reinterpret_cast<uint32_t*>(Clb + (size_t)r1 * ldc + gc) = l1;
            }
        }
    }
}

// ====================== elementwise kernels ======================
__global__ void split_k(const float* __restrict__ s, bf16* __restrict__ h,
                        bf16* __restrict__ l, size_t n4)
{
    for (size_t i = (size_t)blockIdx.x * blockDim.x + threadIdx.x; i < n4;
         i += (size_t)gridDim.x * blockDim.x) {
        float4 v = reinterpret_cast<const float4*>(s)[i];
        uint32_t h0, l0, h1, l1;
        split2(v.x, v.y, h0, l0);
        split2(v.z, v.w, h1, l1);
        reinterpret_cast<uint2*>(h)[i] = make_uint2(h0, h1);
        reinterpret_cast<uint2*>(l)[i] = make_uint2(l0, l1);
    }
}

__global__ void zero_k(uint4* __restrict__ p, size_t n16)
{
    for (size_t i = (size_t)blockIdx.x * blockDim.x + threadIdx.x; i < n16;
         i += (size_t)gridDim.x * blockDim.x)
        p[i] = make_uint4(0, 0, 0, 0);
}

__global__ void padsplit_k(const float* __restrict__ src, bf16* __restrict__ h,
                           bf16* __restrict__ l, int K, int Nsrc, int col0)
{
    int total = K * Nsrc;
    for (int i = blockIdx.x * blockDim.x + threadIdx.x; i < total;
         i += gridDim.x * blockDim.x) {
        int k = i / Nsrc, n = i - k * Nsrc;
        float v = src[i];
        uint32_t u = __float_as_uint(v);
        float lv = v - __uint_as_float(u & 0xFFFF0000u);
        size_t d = (size_t)k * 128 + col0 + n;
        reinterpret_cast<unsigned short*>(h)[d] = (unsigned short)(u >> 16);
        reinterpret_cast<unsigned short*>(l)[d] = (unsigned short)(pack_bf16x2(lv, lv) & 0xFFFFu);
    }
}

__global__ void norms_k(const float* __restrict__ G, float* __restrict__ nrm)
{
    int i = blockIdx.x * blockDim.x + threadIdx.x;
    if (i < BQ * PP) {
        int b = i >> 10, p = i & (PP - 1);
        nrm[i] = sqrtf(G[((size_t)b * PP + p) * PP + p]);
    }
}

// mirror upper->lower for symmetric gram buffers
__global__ __launch_bounds__(256)
void mirror_k(float* __restrict__ A, float* __restrict__ B)
{
    int tj = blockIdx.x, ti = blockIdx.y, b = blockIdx.z;
    if (ti <= tj || (ti >> 2) == (tj >> 2)) return;
    __shared__ float ta[32][33], tb[32][33];
    int tx = threadIdx.x & 31, ty = threadIdx.x >> 5;
    size_t base = (size_t)b * PP * PP;
#pragma unroll
    for (int it = 0; it < 4; it++) {
        int r = ty + it * 8;
        size_t src = base + (size_t)(tj * 32 + r) * PP + ti * 32 + tx;
        ta[r][tx] = A[src];
        tb[r][tx] = B[src];
    }
    __syncthreads();
#pragma unroll
    for (int it = 0; it < 4; it++) {
        int r = ty + it * 8;
        size_t dst = base + (size_t)(ti * 32 + r) * PP + tj * 32 + tx;
        A[dst] = ta[tx][r];
        B[dst] = tb[tx][r];
    }
}

__global__ void redheads_k(const float* __restrict__ hp1, const float* __restrict__ hp2,
                           const float* __restrict__ fab, const float* __restrict__ fcb,
                           const float* __restrict__ frb, float* __restrict__ out)
{
    int i = blockIdx.x * blockDim.x + threadIdx.x;
    int total = BQ * PP * 81;
    if (i >= total) return;
    int row = i / 81, col = i - row * 81;
    float v;
    if (col < 21) {
        v = fab[col];
#pragma unroll
        for (int s = 0; s < 2; s++)
            v += hp1[((size_t)s * BQ * PP + row) * 128 + col];
    } else {
        int c2 = col - 21;
        v = (c2 < 20) ? fcb[c2] : frb[c2 - 20];
#pragma unroll
        for (int s = 0; s < 4; s++)
            v += hp2[((size_t)s * BQ * PP + row) * 128 + c2];
    }
    out[i] = v;
}

// ---------------- graph construction ----------------
__device__ __forceinline__ void warp_argmin(float& v, int& l)
{
#pragma unroll
    for (int off = 16; off; off >>= 1) {
        float ov = __shfl_down_sync(0xffffffffu, v, off);
        int ol = __shfl_down_sync(0xffffffffu, l, off);
        if (ov < v) { v = ov; l = ol; }
    }
    v = __shfl_sync(0xffffffffu, v, 0);
    l = __shfl_sync(0xffffffffu, l, 0);
}
__device__ __forceinline__ void warp_argmax(float& v, int& l)
{
#pragma unroll
    for (int off = 16; off; off >>= 1) {
        float ov = __shfl_down_sync(0xffffffffu, v, off);
        int ol = __shfl_down_sync(0xffffffffu, l, off);
        if (ov > v) { v = ov; l = ol; }
    }
    v = __shfl_sync(0xffffffffu, v, 0);
    l = __shfl_sync(0xffffffffu, l, 0);
}

__global__ __launch_bounds__(128)
void build_adj_k(const float* __restrict__ iou, const float* __restrict__ dis,
                 const float* __restrict__ acos_, const float* __restrict__ ccos_,
                 const float* __restrict__ na, const float* __restrict__ nc,
                 const int* __restrict__ props,
                 bf16* __restrict__ awh, bf16* __restrict__ awl,
                 bf16* __restrict__ cwh, bf16* __restrict__ cwl)
{
    __shared__ float sio[4][PP];
    int warp = threadIdx.x >> 5, lane = threadIdx.x & 31;
    int row = blockIdx.x * 4 + warp;
    if (row >= BQ * PP) return;
    int b = row >> 10;
    int p = row & (PP - 1);
    const float* iour = iou + (size_t)row * PP;
    const float* disr = dis + (size_t)row * PP;
    const float* ar = acos_ + (size_t)row * PP;
    const float* cr = ccos_ + (size_t)row * PP;
    const float* nab = na + (b << 10);
    const float* ncb = nc + (b << 10);
    float npa = nab[p], npc = ncb[p];
    int pn = props[b];
    bool pv = p < pn;

    float* io_s = sio[warp];
    for (int q = lane; q < PP; q += 32) io_s[q] = iour[q];
    __syncwarp();

    float dv[6]; int di[6];
#pragma unroll
    for (int j = 0; j < 6; j++) { dv[j] = 3.0e38f; di[j] = -1; }
    float sv[2] = {-3.0e38f, -3.0e38f};
    int si[2] = {-1, -1};

    for (int q = lane; q < PP; q += 32) {
        float io = io_s[q];
        bool ip = io > 0.0f;
        bool qv = q < pn;
        bool v2 = pv && qv;

        float dm = v2 ? (ip ? 2.0f : disr[q]) : 1.0e9f;
        if (dm < dv[5]) {
            dv[5] = dm; di[5] = q;
#pragma unroll
            for (int j = 5; j > 0; j--) {
                if (dv[j] < dv[j - 1]) {
                    float tv = dv[j]; dv[j] = dv[j - 1]; dv[j - 1] = tv;
                    int ti = di[j]; di[j] = di[j - 1]; di[j - 1] = ti;
                }
            }
        }
        float av = ar[q] / (npa * nab[q] + 1e-6f);
        float sm = v2 ? (ip ? 0.0f : (av - (q == p ? 1.0f : 0.0f))) : -1.0e9f;
        if (sm > sv[1]) {
            if (sm > sv[0]) { sv[1] = sv[0]; si[1] = si[0]; sv[0] = sm; si[0] = q; }
            else            { sv[1] = sm; si[1] = q; }
        }
    }

    int sel[8];
    {
        int ptr = 0;
        for (int k = 0; k < 6; k++) {
            float cv = (ptr < 6) ? dv[ptr] : 3.0e38f;
            int ci = (ptr < 6) ? di[ptr] : -1;
            float v = cv; int l = lane;
            warp_argmin(v, l);
            sel[k] = __shfl_sync(0xffffffffu, ci, l);
            if (lane == l) ptr++;
        }
    }
    {
        int ptr = 0;
        for (int k = 0; k < 2; k++) {
            float cv = (ptr < 2) ? sv[ptr] : -3.0e38f;
            int ci = (ptr < 2) ? si[ptr] : -1;
            float v = cv; int l = lane;
            warp_argmax(v, l);
            sel[6 + k] = __shfl_sync(0xffffffffu, ci, l);
            if (lane == l) ptr++;
        }
    }
#pragma unroll
    for (int k = 0; k < 8; k++) {
        int q = sel[k];
        bool ok = (q >= 0) && pv && (q < pn) && !(io_s[q] > 0.0f);
        sel[k] = ok ? q : -1;
    }

    unsigned mbits = 0;
    for (int i = 0; i < 32; i++) {
        int q = lane + 32 * i;
        float io = io_s[q];
        bool bit = (q != p) && (io > 0.7f);
#pragma unroll
        for (int k = 0; k < 8; k++) bit |= (sel[k] == q);
        mbits |= (bit ? 1u : 0u) << i;
    }
    int cnt = __popc(mbits);
#pragma unroll
    for (int off = 16; off; off >>= 1) cnt += __shfl_xor_sync(0xffffffffu, cnt, off);
    float inv = 1.0f / ((float)cnt + 1e-6f);

    unsigned short* ah_ = reinterpret_cast<unsigned short*>(awh) + (size_t)row * PP;
    unsigned short* al_ = reinterpret_cast<unsigned short*>(awl) + (size_t)row * PP;
    unsigned short* ch_ = reinterpret_cast<unsigned short*>(cwh) + (size_t)row * PP;
    unsigned short* cl_ = reinterpret_cast<unsigned short*>(cwl) + (size_t)row * PP;
    for (int i = 0; i < 32; i++) {
        int q = lane + 32 * i;
        float m = ((mbits >> i) & 1u) ? inv : 0.0f;
        if (q == p) m += 1.0f;
        float av = ar[q] / (npa * nab[q] + 1e-6f);
        float cv = cr[q] / (npc * ncb[q] + 1e-6f);
        float a = fmaxf(av * m, 0.f);
        float c = fmaxf(cv * m, 0.f);
        uint32_t ua = __float_as_uint(a);
        uint32_t uc = __float_as_uint(c);
        float la = a - __uint_as_float(ua & 0xFFFF0000u);
        float lc = c - __uint_as_float(uc & 0xFFFF0000u);
        ah_[q] = (unsigned short)(ua >> 16);
        al_[q] = (unsigned short)(pack_bf16x2(la, la) & 0xFFFFu);
        ch_[q] = (unsigned short)(uc >> 16);
        cl_[q] = (unsigned short)(pack_bf16x2(lc, lc) & 0xFFFFu);
    }
}

// ---------------- host orchestration ----------------
static void gx(int tbk, const bf16* Ah, const bf16* Al, const bf16* Bh, const bf16* Bl,
               float* C, bf16* Ch, bf16* Cl,
               int M, int N, int K, int Klen, int symm,
               long sA, long sB, long sC, int batch,
               const float* bias, const float* resid, long sR,
               int ldc, int relu)
{
    int smem = NSTAGE * (ASTG + (tbk ? BSTG1 : BSTG0));
    dim3 grid(Klen ? K / Klen : N / 128, M / 128, batch);
    if (tbk) {
        cudaFuncSetAttribute(gemmx_k<1>, cudaFuncAttributeMaxDynamicSharedMemorySize, smem);
        gemmx_k<1><<<grid, 512, smem>>>(Ah, Al, Bh, Bl, C, Ch, Cl, N, K, Klen, symm,
                                        sA, sB, sC, bias, resid, sR, ldc, relu);
    } else {
        cudaFuncSetAttribute(gemmx_k<0>, cudaFuncAttributeMaxDynamicSharedMemorySize, smem);
        gemmx_k<0><<<grid, 512, smem>>>(Ah, Al, Bh, Bl, C, Ch, Cl, N, K, Klen, symm,
                                        sA, sB, sC, bias, resid, sR, ldc, relu);
    }
}

#define SYM(var, sym) cudaGetSymbolAddress((void**)&var, sym)

extern "C" void kernel_launch(void* const* d_in, const int* in_sizes, int n_in,
                              void* d_out, int out_size)
{
    const float* act   = (const float*)d_in[0];
    const float* comp  = (const float*)d_in[1];
    const float* iou   = (const float*)d_in[2];
    const float* dis   = (const float*)d_in[3];
    const int*   props = (const int*)d_in[4];
    const float* a_w1  = (const float*)d_in[5];
    const float* a_b1  = (const float*)d_in[6];
    const float* a_w2  = (const float*)d_in[7];
    const float* a_b2  = (const float*)d_in[8];
    const float* c_w1  = (const float*)d_in[9];
    const float* c_b1  = (const float*)d_in[10];
    const float* c_w2  = (const float*)d_in[11];
    const float* c_b2  = (const float*)d_in[12];
    const float* fa_w  = (const float*)d_in[13];
    const float* fa_b  = (const float*)d_in[14];
    const float* fc_w  = (const float*)d_in[15];
    const float* fc_b  = (const float*)d_in[16];
    const float* fr_w  = (const float*)d_in[17];
    const float* fr_b  = (const float*)d_in[18];
    float* out = (float*)d_out;

    float *acos_, *ccos_, *na, *nc, *hp1, *hp2;
    bf16 *ah, *al, *ch_, *cl_, *aadjh, *aadjl, *cadjh, *cadjl;
    bf16 *w1ah, *w1al, *w2ah, *w2al, *w1ch, *w1cl, *w2ch, *w2cl;
    bf16 *t1h, *t1l, *t2h, *t2l, *t3h, *t3l, *ofah, *ofal, *ofch, *ofcl;
    bf16 *wp1h, *wp1l, *wp2h, *wp2l;
    SYM(acos_, g_acos); SYM(ccos_, g_ccos); SYM(na, g_na); SYM(nc, g_nc);
    SYM(ah, g_ah); SYM(al, g_al); SYM(ch_, g_ch); SYM(cl_, g_cl);
    SYM(aadjh, g_aadjh); SYM(aadjl, g_aadjl); SYM(cadjh, g_cadjh); SYM(cadjl, g_cadjl);
    SYM(w1ah, g_w1ah); SYM(w1al, g_w1al); SYM(w2ah, g_w2ah); SYM(w2al, g_w2al);
    SYM(w1ch, g_w1ch); SYM(w1cl, g_w1cl); SYM(w2ch, g_w2ch); SYM(w2cl, g_w2cl);
    SYM(t1h, g_t1h); SYM(t1l, g_t1l); SYM(t2h, g_t2h); SYM(t2l, g_t2l);
    SYM(t3h, g_t3h); SYM(t3l, g_t3l);
    SYM(ofah, g_ofah); SYM(ofal, g_ofal); SYM(ofch, g_ofch); SYM(ofcl, g_ofcl);
    SYM(wp1h, g_wp1h); SYM(wp1l, g_wp1l); SYM(wp2h, g_wp2h); SYM(wp2l, g_wp2l);
    SYM(hp1, g_hp1); SYM(hp2, g_hp2);

    // 0) split inputs + weights to bf16 hi/lo
    split_k<<<1024, 256>>>(act, ah, al, (size_t)BQ * PP * DDA / 4);
    split_k<<<2048, 256>>>(comp, ch_, cl_, (size_t)BQ * PP * DDC / 4);
    split_k<<<256, 256>>>(a_w1, w1ah, w1al, (size_t)DDA * HID / 4);
    split_k<<<256, 256>>>(a_w2, w2ah, w2al, (size_t)HID * DDA / 4);
    split_k<<<512, 256>>>(c_w1, w1ch, w1cl, (size_t)DDC * HID / 4);
    split_k<<<512, 256>>>(c_w2, w2ch, w2cl, (size_t)HID * DDC / 4);

    zero_k<<<64, 256>>>((uint4*)wp1h, (size_t)DDA * 128 * 2 / 16);
    zero_k<<<64, 256>>>((uint4*)wp1l, (size_t)DDA * 128 * 2 / 16);
    zero_k<<<128, 256>>>((uint4*)wp2h, (size_t)DDC * 128 * 2 / 16);
    zero_k<<<128, 256>>>((uint4*)wp2l, (size_t)DDC * 128 * 2 / 16);
    padsplit_k<<<128, 256>>>(fa_w, wp1h, wp1l, DDA, 21, 0);
    padsplit_k<<<256, 256>>>(fc_w, wp2h, wp2l, DDC, 20, 0);
    padsplit_k<<<512, 256>>>(fr_w, wp2h, wp2l, DDC, 40, 20);

    // 1) Gram matrices, symmetric + mirror
    gx(1, ah, al, ah, al, acos_, 0, 0, PP, PP, DDA, 0, 1,
       (long)PP * DDA, (long)PP * DDA, (long)PP * PP, BQ, 0, 0, 0, PP, 0);
    gx(1, ch_, cl_, ch_, cl_, ccos_, 0, 0, PP, PP, DDC, 0, 1,
       (long)PP * DDC, (long)PP * DDC, (long)PP * PP, BQ, 0, 0, 0, PP, 0);
    mirror_k<<<dim3(32, 32, BQ), 256>>>(acos_, ccos_);

    // 2) norms
    norms_k<<<(BQ * PP + 255) / 256, 256>>>(acos_, na);
    norms_k<<<(BQ * PP + 255) / 256, 256>>>(ccos_, nc);

    // 3) graph construction (normalization fused)
    build_adj_k<<<BQ * PP / 4, 128>>>(iou, dis, acos_, ccos_, na, nc, props,
                                      aadjh, aadjl, cadjh, cadjl);

    // 4) Act GCN chain
    gx(0, ah, al, w1ah, w1al, 0, t1h, t1l, BQ * PP, HID, DDA, 0, 0,
       0, 0, 0, 1, 0, 0, 0, HID, 0);
    gx(0, aadjh, aadjl, t1h, t1l, 0, t2h, t2l, PP, HID, PP, 0, 0,
       (long)PP * PP, (long)PP * HID, (long)PP * HID, BQ, a_b1, 0, 0, HID, 1);
    gx(0, t2h, t2l, w2ah, w2al, 0, t3h, t3l, BQ * PP, DDA, HID, 0, 0,
       0, 0, 0, 1, 0, 0, 0, DDA, 0);
    gx(0, aadjh, aadjl, t3h, t3l, 0, ofah, ofal, PP, DDA, PP, 0, 0,
       (long)PP * PP, (long)PP * DDA, (long)PP * DDA, BQ,
       a_b2, act, (long)PP * DDA, DDA, 0);
    gx(0, ofah, ofal, wp1h, wp1l, hp1, 0, 0, BQ * PP, 128, DDA, 512, 0,
       0, 0, (long)BQ * PP * 128, 1, 0, 0, 0, 128, 0);

    // 5) Comp GCN chain
    gx(0, ch_, cl_, w1ch, w1cl, 0, t1h, t1l, BQ * PP, HID, DDC, 0, 0,
       0, 0, 0, 1, 0, 0, 0, HID, 0);
    gx(0, cadjh, cadjl, t1h, t1l, 0, t2h, t2l, PP, HID, PP, 0, 0,
       (long)PP * PP, (long)PP * HID, (long)PP * HID, BQ, c_b1, 0, 0, HID, 1);
    gx(0, t2h, t2l, w2ch, w2cl, 0, t3h, t3l, BQ * PP, DDC, HID, 0, 0,
       0, 0, 0, 1, 0, 0, 0, DDC, 0);
    gx(0, cadjh, cadjl, t3h, t3l, 0, ofch, ofcl, PP, DDC, PP, 0, 0,
       (long)PP * PP, (long)PP * DDC, (long)PP * DDC, BQ,
       c_b2, comp, (long)PP * DDC, DDC, 0);
    gx(0, ofch, ofcl, wp2h, wp2l, hp2, 0, 0, BQ * PP, 128, DDC, 768, 0,
       0, 0, (long)BQ * PP * 128, 1, 0, 0, 0, 128, 0);

    // 6) head reduction -> out
    redheads_k<<<(BQ * PP * 81 + 255) / 256, 256>>>(hp1, hp2, fa_b, fc_b, fr_b, out);
}

// round 7
// speedup vs baseline: 1.0258x; 1.0258x over previous
#include <cuda_runtime.h>
#include <cuda_bf16.h>
#include <math.h>
#include <stdint.h>

#define BQ 4
#define PP 1024
#define DDA 1024
#define DDC 3072
#define HID 512
typedef __nv_bfloat16 bf16;

// ---------------- scratch (static device memory, no allocation) ----------------
__device__ float g_acos[(size_t)BQ*PP*PP];
__device__ float g_ccos[(size_t)BQ*PP*PP];
__device__ float g_na[BQ*PP];
__device__ float g_nc[BQ*PP];
__device__ bf16 g_ah[(size_t)BQ*PP*DDA], g_al[(size_t)BQ*PP*DDA];
__device__ bf16 g_ch[(size_t)BQ*PP*DDC], g_cl[(size_t)BQ*PP*DDC];
__device__ bf16 g_aadjh[(size_t)BQ*PP*PP], g_aadjl[(size_t)BQ*PP*PP];
__device__ bf16 g_cadjh[(size_t)BQ*PP*PP], g_cadjl[(size_t)BQ*PP*PP];
__device__ bf16 g_w1ah[DDA*HID], g_w1al[DDA*HID];
__device__ bf16 g_w2ah[HID*DDA], g_w2al[HID*DDA];
__device__ bf16 g_w1ch[DDC*HID], g_w1cl[DDC*HID];
__device__ bf16 g_w2ch[HID*DDC], g_w2cl[HID*DDC];
__device__ bf16 g_t1h[(size_t)BQ*PP*HID], g_t1l[(size_t)BQ*PP*HID];
__device__ bf16 g_t2h[(size_t)BQ*PP*HID], g_t2l[(size_t)BQ*PP*HID];
__device__ bf16 g_t3h[(size_t)BQ*PP*DDC], g_t3l[(size_t)BQ*PP*DDC];
__device__ bf16 g_ofah[(size_t)BQ*PP*DDA], g_ofal[(size_t)BQ*PP*DDA];
__device__ bf16 g_ofch[(size_t)BQ*PP*DDC], g_ofcl[(size_t)BQ*PP*DDC];
__device__ bf16 g_wp1h[DDA*128], g_wp1l[DDA*128];
__device__ bf16 g_wp2h[DDC*128], g_wp2l[DDC*128];
__device__ float g_hp1[(size_t)4*BQ*PP*128];
__device__ float g_hp2[(size_t)8*BQ*PP*128];
__device__ float g_kp[(size_t)2*BQ*PP*HID];

// ====================== low-level helpers ======================
__device__ __forceinline__ uint32_t smem_u32(const void* p) {
    uint32_t a;
    asm("{ .reg .u64 t; cvta.to.shared.u64 t, %1; cvt.u32.u64 %0, t; }" : "=r"(a) : "l"(p));
    return a;
}
__device__ __forceinline__ uint32_t pack_bf16x2(float lo_e, float hi_e) {
    uint32_t r;
    asm("cvt.rn.bf16x2.f32 %0, %1, %2;" : "=r"(r) : "f"(hi_e), "f"(lo_e));
    return r;
}
__device__ __forceinline__ void split2(float x, float y, uint32_t& h, uint32_t& l) {
    uint32_t ux = __float_as_uint(x), uy = __float_as_uint(y);
    h = __byte_perm(ux, uy, 0x7632);
    float lx = x - __uint_as_float(ux & 0xFFFF0000u);
    float ly = y - __uint_as_float(uy & 0xFFFF0000u);
    l = pack_bf16x2(lx, ly);
}
__device__ __forceinline__ void ldmx4(uint32_t* r, uint32_t addr) {
    asm volatile("ldmatrix.sync.aligned.m8n8.x4.shared.b16 {%0,%1,%2,%3}, [%4];"
                 : "=r"(r[0]), "=r"(r[1]), "=r"(r[2]), "=r"(r[3]) : "r"(addr));
}
__device__ __forceinline__ void ldmx4t(uint32_t* r, uint32_t addr) {
    asm volatile("ldmatrix.sync.aligned.m8n8.x4.trans.shared.b16 {%0,%1,%2,%3}, [%4];"
                 : "=r"(r[0]), "=r"(r[1]), "=r"(r[2]), "=r"(r[3]) : "r"(addr));
}
__device__ __forceinline__ void mma_bf16(float* c, const uint32_t* a, const uint32_t* b) {
    asm volatile(
        "mma.sync.aligned.m16n8k16.row.col.f32.bf16.bf16.f32 "
        "{%0,%1,%2,%3}, {%4,%5,%6,%7}, {%8,%9}, {%0,%1,%2,%3};"
        : "+f"(c[0]), "+f"(c[1]), "+f"(c[2]), "+f"(c[3])
        : "r"(a[0]), "r"(a[1]), "r"(a[2]), "r"(a[3]), "r"(b[0]), "r"(b[1]));
}
__device__ __forceinline__ void cp16(uint32_t dst, const void* src) {
    asm volatile("cp.async.cg.shared.global [%0], [%1], 16;" :: "r"(dst), "l"(src) : "memory");
}
#define CP_COMMIT() asm volatile("cp.async.commit_group;" ::: "memory")

// ====================== bf16x3 multistage mma GEMM ======================
// TBK=1: B hi/lo [N,K]. TBK=0: B hi/lo [K,N].
// TM=1: CTA 128x128, 8 warps 2x4 (64x32 warp tile), 4 stages.
// TM=2: CTA 256x128, 8 warps 4x2 (64x64 warp tile), 3 stages.
// symm: skip blocks bx<by (TM=1 square only).
// Klen>0: K-split: blockIdx.x = kslice*nxt + ntile; fp32 partial at C + kslice*sC.
#define AROWB 80

template<int TBK, int TM>
__global__ __launch_bounds__(256, 1)
void gemmx_k(const bf16* __restrict__ Ah, const bf16* __restrict__ Al,
             const bf16* __restrict__ Bh, const bf16* __restrict__ Bl,
             float* __restrict__ C, bf16* __restrict__ Ch, bf16* __restrict__ Cl,
             int N, int K, int Klen, int symm,
             long sA, long sB, long sC,
             const float* __restrict__ bias,
             const float* __restrict__ resid, long sR,
             int ldc, int relu_flag)
{
    if (!Klen && symm && blockIdx.x < blockIdx.y) return;
    constexpr int ATL = TM * 10240;           // A hi (or lo) tile bytes
    constexpr int ASTGT = 2 * ATL;
    constexpr int BSTG = TBK ? 20480 : 16384;
    constexpr int SB = ASTGT + BSTG;
    constexpr int NST = (TM == 2) ? 3 : 4;
    constexpr int NFR = (TM == 2) ? 8 : 4;
    extern __shared__ char sm[];
    uint32_t smb = smem_u32(sm);

    const int tid = threadIdx.x;
    const int lane = tid & 31;
    const int wid = tid >> 5;
    const int wm = (TM == 2) ? (wid >> 1) * 64 : (wid >> 2) * 64;
    const int wn = (TM == 2) ? (wid & 1) * 64 : (wid & 3) * 32;

    long bz = blockIdx.z;
    const int bm = blockIdx.y * (128 * TM);
    const int nxt = N >> 7;
    int bn, kbase, kslice = 0;
    if (Klen) {
        kslice = (int)blockIdx.x / nxt;
        bn = ((int)blockIdx.x - kslice * nxt) << 7;
        kbase = kslice * Klen;
    } else {
        bn = (int)blockIdx.x << 7;
        kbase = 0;
    }
    const int KL = Klen ? Klen : K;

    const bf16* Ahb = Ah + bz * sA + (size_t)bm * K + kbase;
    const bf16* Alb = Al + bz * sA + (size_t)bm * K + kbase;
    const bf16* Bhb = TBK ? (Bh + bz * sB + (size_t)bn * K + kbase)
                          : (Bh + bz * sB + (size_t)kbase * N + bn);
    const bf16* Blb = TBK ? (Bl + bz * sB + (size_t)bn * K + kbase)
                          : (Bl + bz * sB + (size_t)kbase * N + bn);
    float* Cb = C ? (Klen ? C + (size_t)kslice * sC : C + bz * sC) : (float*)0;
    bf16* Chb = Ch ? Ch + bz * sC : (bf16*)0;
    bf16* Clb = Cl ? Cl + bz * sC : (bf16*)0;
    const float* Rb = resid ? resid + bz * sR : (const float*)0;

    float acc[4][NFR][4];
#pragma unroll
    for (int i = 0; i < 4; i++)
#pragma unroll
        for (int j = 0; j < NFR; j++)
#pragma unroll
            for (int r = 0; r < 4; r++) acc[i][j][r] = 0.f;

    const int nch = KL >> 5;

    auto load_stage = [&](int kt, int s) {
        uint32_t base = smb + (uint32_t)s * SB;
        int k0 = kt << 5;
        constexpr int SH = (TM == 2) ? 10 : 9;
#pragma unroll
        for (int it = 0; it < TM * 4; it++) {
            int id = it * 256 + tid;
            int hl = id >> SH;
            int rid = id & ((1 << SH) - 1);
            int row = rid >> 2, c = rid & 3;
            const bf16* src = (hl ? Alb : Ahb) + (size_t)row * K + k0 + c * 8;
            cp16(base + hl * ATL + row * AROWB + c * 16, src);
        }
        if (TBK) {
#pragma unroll
            for (int it = 0; it < 4; it++) {
                int id = it * 256 + tid;
                int hl = id >> 9, rid = id & 511;
                int row = rid >> 2, c = rid & 3;
                const bf16* src = (hl ? Blb : Bhb) + (size_t)row * K + k0 + c * 8;
                cp16(base + ASTGT + hl * 10240 + row * AROWB + c * 16, src);
            }
        } else {
#pragma unroll
            for (int it = 0; it < 4; it++) {
                int id = it * 256 + tid;
                int hl = id >> 9, rid = id & 511;
                int k = rid >> 4, c = rid & 15;
                cp16(base + ASTGT + hl * 8192 + k * 256 + ((c ^ (k & 7)) << 4),
                     (hl ? Blb : Bhb) + (size_t)(k0 + k) * N + c * 8);
            }
        }
        CP_COMMIT();
    };

#pragma unroll
    for (int s = 0; s < NST - 1; s++) load_stage(s, s);

    int sc = 0, sl = NST - 1;
    for (int kt = 0; kt < nch; kt++) {
        if (NST == 3)
            asm volatile("cp.async.wait_group 1;" ::: "memory");
        else
            asm volatile("cp.async.wait_group 2;" ::: "memory");
        __syncthreads();
        if (kt + NST - 1 < nch) {
            load_stage(kt + NST - 1, sl);
            sl = (sl + 1 == NST) ? 0 : sl + 1;
        } else {
            CP_COMMIT();
        }
        uint32_t aB = smb + (uint32_t)sc * SB;
        uint32_t bB = aB + ASTGT;
        sc = (sc + 1 == NST) ? 0 : sc + 1;

#pragma unroll
        for (int kh = 0; kh < 2; kh++) {
            uint32_t ahi[4][4], alo[4][4];
            {
                int arow = wm + (lane & 15);
                uint32_t aoff = (uint32_t)(kh * 32 + ((lane >> 4) << 4));
#pragma unroll
                for (int i = 0; i < 4; i++) {
                    uint32_t ro = (uint32_t)(arow + i * 16) * AROWB + aoff;
                    ldmx4(ahi[i], aB + ro);
                    ldmx4(alo[i], aB + ATL + ro);
                }
            }
#pragma unroll
            for (int jp = 0; jp < NFR / 2; jp++) {
                uint32_t bh2[4], bl2[4];
                if (TBK) {
                    int row = wn + jp * 16 + ((lane >> 4) << 3) + (lane & 7);
                    uint32_t ro = (uint32_t)row * AROWB
                                + (uint32_t)(kh * 32 + (((lane >> 3) & 1) << 4));
                    ldmx4(bh2, bB + ro);
                    ldmx4(bl2, bB + 10240 + ro);
                } else {
                    int k = kh * 16 + ((lane >> 3) & 1) * 8 + (lane & 7);
                    uint32_t kro = (uint32_t)k << 8;
                    int colblk = (wn >> 3) + 2 * jp + (lane >> 4);
                    uint32_t ad = kro + ((uint32_t)(colblk ^ (k & 7)) << 4);
                    ldmx4t(bh2, bB + ad);
                    ldmx4t(bl2, bB + 8192 + ad);
                }
                int j0 = 2 * jp, j1 = 2 * jp + 1;
#pragma unroll
                for (int i = 0; i < 4; i++) {
                    mma_bf16(acc[i][j0], ahi[i], bh2 + 0);
                    mma_bf16(acc[i][j1], ahi[i], bh2 + 2);
                }
#pragma unroll
                for (int i = 0; i < 4; i++) {
                    mma_bf16(acc[i][j0], ahi[i], bl2 + 0);
                    mma_bf16(acc[i][j1], ahi[i], bl2 + 2);
                }
#pragma unroll
                for (int i = 0; i < 4; i++) {
                    mma_bf16(acc[i][j0], alo[i], bh2 + 0);
                    mma_bf16(acc[i][j1], alo[i], bh2 + 2);
                }
            }
        }
    }

    // ---- epilogue ----
#pragma unroll
    for (int i = 0; i < 4; i++) {
        int r0 = bm + wm + i * 16 + (lane >> 2);
        int r1 = r0 + 8;
#pragma unroll
        for (int j = 0; j < NFR; j++) {
            int gc = bn + wn + j * 8 + (lane & 3) * 2;
            float2 v0 = make_float2(acc[i][j][0], acc[i][j][1]);
            float2 v1 = make_float2(acc[i][j][2], acc[i][j][3]);
            if (bias) {
                float2 bv = *reinterpret_cast<const float2*>(bias + gc);
                v0.x += bv.x; v0.y += bv.y;
                v1.x += bv.x; v1.y += bv.y;
            }
            if (Rb) {
                float2 q0 = *reinterpret_cast<const float2*>(Rb + (size_t)r0 * ldc + gc);
                float2 q1 = *reinterpret_cast<const float2*>(Rb + (size_t)r1 * ldc + gc);
                v0.x += q0.x; v0.y += q0.y;
                v1.x += q1.x; v1.y += q1.y;
            }
            if (relu_flag) {
                v0.x = fmaxf(v0.x, 0.f); v0.y = fmaxf(v0.y, 0.f);
                v1.x = fmaxf(v1.x, 0.f); v1.y = fmaxf(v1.y, 0.f);
            }
            if (Cb) {
                *reinterpret_cast<float2*>(Cb + (size_t)r0 * ldc + gc) = v0;
                *reinterpret_cast<float2*>(Cb + (size_t)r1 * ldc + gc) = v1;
            }
            if (Chb) {
                uint32_t h0, l0, h1, l1;
                split2(v0.x, v0.y, h0, l0);
                split2(v1.x, v1.y, h1, l1);
                *reinterpret_cast<uint32_t*>(Chb + (size_t)r0 * ldc + gc) = h0;
                *reinterpret_cast<uint32_t*>(Clb + (size_t)r0 * ldc + gc) = l0;
                *reinterpret_cast<uint32_t*>(Chb + (size_t)r1 * ldc + gc) = h1;
                *reinterpret_cast<uint32_t*>(Clb + (size_t)r1 * ldc + gc) = l1;
            }
        }
    }
}

// ====================== elementwise kernels ======================
__global__ void split_k(const float* __restrict__ s, bf16* __restrict__ h,
                        bf16* __restrict__ l, size_t n4)
{
    for (size_t i = (size_t)blockIdx.x * blockDim.x + threadIdx.x; i < n4;
         i += (size_t)gridDim.x * blockDim.x) {
        float4 v = reinterpret_cast<const float4*>(s)[i];
        uint32_t h0, l0, h1, l1;
        split2(v.x, v.y, h0, l0);
        split2(v.z, v.w, h1, l1);
        reinterpret_cast<uint2*>(h)[i] = make_uint2(h0, h1);
        reinterpret_cast<uint2*>(l)[i] = make_uint2(l0, l1);
    }
}

// sum nsl K-slice partials -> split bf16 hi/lo
__global__ void redsplit_k(const float* __restrict__ p, size_t sstride4, int nsl,
                           bf16* __restrict__ h, bf16* __restrict__ l, size_t n4)
{
    for (size_t i = (size_t)blockIdx.x * blockDim.x + threadIdx.x; i < n4;
         i += (size_t)gridDim.x * blockDim.x) {
        float4 v = reinterpret_cast<const float4*>(p)[i];
        for (int s = 1; s < nsl; s++) {
            float4 w = reinterpret_cast<const float4*>(p)[s * sstride4 + i];
            v.x += w.x; v.y += w.y; v.z += w.z; v.w += w.w;
        }
        uint32_t h0, l0, h1, l1;
        split2(v.x, v.y, h0, l0);
        split2(v.z, v.w, h1, l1);
        reinterpret_cast<uint2*>(h)[i] = make_uint2(h0, h1);
        reinterpret_cast<uint2*>(l)[i] = make_uint2(l0, l1);
    }
}

__global__ void zero_k(uint4* __restrict__ p, size_t n16)
{
    for (size_t i = (size_t)blockIdx.x * blockDim.x + threadIdx.x; i < n16;
         i += (size_t)gridDim.x * blockDim.x)
        p[i] = make_uint4(0, 0, 0, 0);
}

__global__ void padsplit_k(const float* __restrict__ src, bf16* __restrict__ h,
                           bf16* __restrict__ l, int K, int Nsrc, int col0)
{
    int total = K * Nsrc;
    for (int i = blockIdx.x * blockDim.x + threadIdx.x; i < total;
         i += gridDim.x * blockDim.x) {
        int k = i / Nsrc, n = i - k * Nsrc;
        float v = src[i];
        uint32_t u = __float_as_uint(v);
        float lv = v - __uint_as_float(u & 0xFFFF0000u);
        size_t d = (size_t)k * 128 + col0 + n;
        reinterpret_cast<unsigned short*>(h)[d] = (unsigned short)(u >> 16);
        reinterpret_cast<unsigned short*>(l)[d] = (unsigned short)(pack_bf16x2(lv, lv) & 0xFFFFu);
    }
}

__global__ void norms_k(const float* __restrict__ G, float* __restrict__ nrm)
{
    int i = blockIdx.x * blockDim.x + threadIdx.x;
    if (i < BQ * PP) {
        int b = i >> 10, p = i & (PP - 1);
        nrm[i] = sqrtf(G[((size_t)b * PP + p) * PP + p]);
    }
}

__global__ __launch_bounds__(256)
void mirror_k(float* __restrict__ A, float* __restrict__ B)
{
    int tj = blockIdx.x, ti = blockIdx.y, b = blockIdx.z;
    if (ti <= tj || (ti >> 2) == (tj >> 2)) return;
    __shared__ float ta[32][33], tb[32][33];
    int tx = threadIdx.x & 31, ty = threadIdx.x >> 5;
    size_t base = (size_t)b * PP * PP;
#pragma unroll
    for (int it = 0; it < 4; it++) {
        int r = ty + it * 8;
        size_t src = base + (size_t)(tj * 32 + r) * PP + ti * 32 + tx;
        ta[r][tx] = A[src];
        tb[r][tx] = B[src];
    }
    __syncthreads();
#pragma unroll
    for (int it = 0; it < 4; it++) {
        int r = ty + it * 8;
        size_t dst = base + (size_t)(ti * 32 + r) * PP + tj * 32 + tx;
        A[dst] = ta[tx][r];
        B[dst] = tb[tx][r];
    }
}

__global__ void redheads_k(const float* __restrict__ hp1, const float* __restrict__ hp2,
                           const float* __restrict__ fab, const float* __restrict__ fcb,
                           const float* __restrict__ frb, float* __restrict__ out)
{
    int i = blockIdx.x * blockDim.x + threadIdx.x;
    int total = BQ * PP * 81;
    if (i >= total) return;
    int row = i / 81, col = i - row * 81;
    float v;
    if (col < 21) {
        v = fab[col];
#pragma unroll
        for (int s = 0; s < 4; s++)
            v += hp1[((size_t)s * BQ * PP + row) * 128 + col];
    } else {
        int c2 = col - 21;
        v = (c2 < 20) ? fcb[c2] : frb[c2 - 20];
#pragma unroll
        for (int s = 0; s < 8; s++)
            v += hp2[((size_t)s * BQ * PP + row) * 128 + c2];
    }
    out[i] = v;
}

// ---------------- graph construction ----------------
__device__ __forceinline__ void warp_argmin(float& v, int& l)
{
#pragma unroll
    for (int off = 16; off; off >>= 1) {
        float ov = __shfl_down_sync(0xffffffffu, v, off);
        int ol = __shfl_down_sync(0xffffffffu, l, off);
        if (ov < v) { v = ov; l = ol; }
    }
    v = __shfl_sync(0xffffffffu, v, 0);
    l = __shfl_sync(0xffffffffu, l, 0);
}
__device__ __forceinline__ void warp_argmax(float& v, int& l)
{
#pragma unroll
    for (int off = 16; off; off >>= 1) {
        float ov = __shfl_down_sync(0xffffffffu, v, off);
        int ol = __shfl_down_sync(0xffffffffu, l, off);
        if (ov > v) { v = ov; l = ol; }
    }
    v = __shfl_sync(0xffffffffu, v, 0);
    l = __shfl_sync(0xffffffffu, l, 0);
}

__global__ __launch_bounds__(128)
void build_adj_k(const float* __restrict__ iou, const float* __restrict__ dis,
                 const float* __restrict__ acos_, const float* __restrict__ ccos_,
                 const float* __restrict__ na, const float* __restrict__ nc,
                 const int* __restrict__ props,
                 bf16* __restrict__ awh, bf16* __restrict__ awl,
                 bf16* __restrict__ cwh, bf16* __restrict__ cwl)
{
    __shared__ float sio[4][PP];
    int warp = threadIdx.x >> 5, lane = threadIdx.x & 31;
    int row = blockIdx.x * 4 + warp;
    if (row >= BQ * PP) return;
    int b = row >> 10;
    int p = row & (PP - 1);
    const float* iour = iou + (size_t)row * PP;
    const float* disr = dis + (size_t)row * PP;
    const float* ar = acos_ + (size_t)row * PP;
    const float* cr = ccos_ + (size_t)row * PP;
    const float* nab = na + (b << 10);
    const float* ncb = nc + (b << 10);
    float npa = nab[p], npc = ncb[p];
    int pn = props[b];
    bool pv = p < pn;

    float* io_s = sio[warp];
    for (int q = lane; q < PP; q += 32) io_s[q] = iour[q];
    __syncwarp();

    float dv[6]; int di[6];
#pragma unroll
    for (int j = 0; j < 6; j++) { dv[j] = 3.0e38f; di[j] = -1; }
    float sv[2] = {-3.0e38f, -3.0e38f};
    int si[2] = {-1, -1};

    for (int q = lane; q < PP; q += 32) {
        float io = io_s[q];
        bool ip = io > 0.0f;
        bool qv = q < pn;
        bool v2 = pv && qv;

        float dm = v2 ? (ip ? 2.0f : disr[q]) : 1.0e9f;
        if (dm < dv[5]) {
            dv[5] = dm; di[5] = q;
#pragma unroll
            for (int j = 5; j > 0; j--) {
                if (dv[j] < dv[j - 1]) {
                    float tv = dv[j]; dv[j] = dv[j - 1]; dv[j - 1] = tv;
                    int ti = di[j]; di[j] = di[j - 1]; di[j - 1] = ti;
                }
            }
        }
        float av = ar[q] / (npa * nab[q] + 1e-6f);
        float sm = v2 ? (ip ? 0.0f : (av - (q == p ? 1.0f : 0.0f))) : -1.0e9f;
        if (sm > sv[1]) {
            if (sm > sv[0]) { sv[1] = sv[0]; si[1] = si[0]; sv[0] = sm; si[0] = q; }
            else            { sv[1] = sm; si[1] = q; }
        }
    }

    int sel[8];
    {
        int ptr = 0;
        for (int k = 0; k < 6; k++) {
            float cv = (ptr < 6) ? dv[ptr] : 3.0e38f;
            int ci = (ptr < 6) ? di[ptr] : -1;
            float v = cv; int l = lane;
            warp_argmin(v, l);
            sel[k] = __shfl_sync(0xffffffffu, ci, l);
            if (lane == l) ptr++;
        }
    }
    {
        int ptr = 0;
        for (int k = 0; k < 2; k++) {
            float cv = (ptr < 2) ? sv[ptr] : -3.0e38f;
            int ci = (ptr < 2) ? si[ptr] : -1;
            float v = cv; int l = lane;
            warp_argmax(v, l);
            sel[6 + k] = __shfl_sync(0xffffffffu, ci, l);
            if (lane == l) ptr++;
        }
    }
#pragma unroll
    for (int k = 0; k < 8; k++) {
        int q = sel[k];
        bool ok = (q >= 0) && pv && (q < pn) && !(io_s[q] > 0.0f);
        sel[k] = ok ? q : -1;
    }

    unsigned mbits = 0;
    for (int i = 0; i < 32; i++) {
        int q = lane + 32 * i;
        float io = io_s[q];
        bool bit = (q != p) && (io > 0.7f);
#pragma unroll
        for (int k = 0; k < 8; k++) bit |= (sel[k] == q);
        mbits |= (bit ? 1u : 0u) << i;
    }
    int cnt = __popc(mbits);
#pragma unroll
    for (int off = 16; off; off >>= 1) cnt += __shfl_xor_sync(0xffffffffu, cnt, off);
    float inv = 1.0f / ((float)cnt + 1e-6f);

    unsigned short* ah_ = reinterpret_cast<unsigned short*>(awh) + (size_t)row * PP;
    unsigned short* al_ = reinterpret_cast<unsigned short*>(awl) + (size_t)row * PP;
    unsigned short* ch_ = reinterpret_cast<unsigned short*>(cwh) + (size_t)row * PP;
    unsigned short* cl_ = reinterpret_cast<unsigned short*>(cwl) + (size_t)row * PP;
    for (int i = 0; i < 32; i++) {
        int q = lane + 32 * i;
        float m = ((mbits >> i) & 1u) ? inv : 0.0f;
        if (q == p) m += 1.0f;
        float av = ar[q] / (npa * nab[q] + 1e-6f);
        float cv = cr[q] / (npc * ncb[q] + 1e-6f);
        float a = fmaxf(av * m, 0.f);
        float c = fmaxf(cv * m, 0.f);
        uint32_t ua = __float_as_uint(a);
        uint32_t uc = __float_as_uint(c);
        float la = a - __uint_as_float(ua & 0xFFFF0000u);
        float lc = c - __uint_as_float(uc & 0xFFFF0000u);
        ah_[q] = (unsigned short)(ua >> 16);
        al_[q] = (unsigned short)(pack_bf16x2(la, la) & 0xFFFFu);
        ch_[q] = (unsigned short)(uc >> 16);
        cl_[q] = (unsigned short)(pack_bf16x2(lc, lc) & 0xFFFFu);
    }
}

// ---------------- host orchestration ----------------
static void gx(int tbk, int tm,
               const bf16* Ah, const bf16* Al, const bf16* Bh, const bf16* Bl,
               float* C, bf16* Ch, bf16* Cl,
               int M, int N, int K, int Klen, int symm,
               long sA, long sB, long sC, int batch,
               const float* bias, const float* resid, long sR,
               int ldc, int relu)
{
    int SBh = tm * 20480 + (tbk ? 20480 : 16384);
    int NSTh = (tm == 2) ? 3 : 4;
    int smem = NSTh * SBh;
    int nxt = N >> 7;
    int gxd = Klen ? nxt * (K / Klen) : nxt;
    dim3 grid(gxd, M / (128 * tm), batch);
    if (tbk == 1 && tm == 1) {
        cudaFuncSetAttribute(gemmx_k<1, 1>, cudaFuncAttributeMaxDynamicSharedMemorySize, smem);
        gemmx_k<1, 1><<<grid, 256, smem>>>(Ah, Al, Bh, Bl, C, Ch, Cl, N, K, Klen, symm,
                                           sA, sB, sC, bias, resid, sR, ldc, relu);
    } else if (tbk == 0 && tm == 1) {
        cudaFuncSetAttribute(gemmx_k<0, 1>, cudaFuncAttributeMaxDynamicSharedMemorySize, smem);
        gemmx_k<0, 1><<<grid, 256, smem>>>(Ah, Al, Bh, Bl, C, Ch, Cl, N, K, Klen, symm,
                                           sA, sB, sC, bias, resid, sR, ldc, relu);
    } else if (tbk == 0 && tm == 2) {
        cudaFuncSetAttribute(gemmx_k<0, 2>, cudaFuncAttributeMaxDynamicSharedMemorySize, smem);
        gemmx_k<0, 2><<<grid, 256, smem>>>(Ah, Al, Bh, Bl, C, Ch, Cl, N, K, Klen, symm,
                                           sA, sB, sC, bias, resid, sR, ldc, relu);
    } else {
        cudaFuncSetAttribute(gemmx_k<1, 2>, cudaFuncAttributeMaxDynamicSharedMemorySize, smem);
        gemmx_k<1, 2><<<grid, 256, smem>>>(Ah, Al, Bh, Bl, C, Ch, Cl, N, K, Klen, symm,
                                           sA, sB, sC, bias, resid, sR, ldc, relu);
    }
}

#define SYM(var, sym) cudaGetSymbolAddress((void**)&var, sym)

extern "C" void kernel_launch(void* const* d_in, const int* in_sizes, int n_in,
                              void* d_out, int out_size)
{
    const float* act   = (const float*)d_in[0];
    const float* comp  = (const float*)d_in[1];
    const float* iou   = (const float*)d_in[2];
    const float* dis   = (const float*)d_in[3];
    const int*   props = (const int*)d_in[4];
    const float* a_w1  = (const float*)d_in[5];
    const float* a_b1  = (const float*)d_in[6];
    const float* a_w2  = (const float*)d_in[7];
    const float* a_b2  = (const float*)d_in[8];
    const float* c_w1  = (const float*)d_in[9];
    const float* c_b1  = (const float*)d_in[10];
    const float* c_w2  = (const float*)d_in[11];
    const float* c_b2  = (const float*)d_in[12];
    const float* fa_w  = (const float*)d_in[13];
    const float* fa_b  = (const float*)d_in[14];
    const float* fc_w  = (const float*)d_in[15];
    const float* fc_b  = (const float*)d_in[16];
    const float* fr_w  = (const float*)d_in[17];
    const float* fr_b  = (const float*)d_in[18];
    float* out = (float*)d_out;

    float *acos_, *ccos_, *na, *nc, *hp1, *hp2, *kp;
    bf16 *ah, *al, *ch_, *cl_, *aadjh, *aadjl, *cadjh, *cadjl;
    bf16 *w1ah, *w1al, *w2ah, *w2al, *w1ch, *w1cl, *w2ch, *w2cl;
    bf16 *t1h, *t1l, *t2h, *t2l, *t3h, *t3l, *ofah, *ofal, *ofch, *ofcl;
    bf16 *wp1h, *wp1l, *wp2h, *wp2l;
    SYM(acos_, g_acos); SYM(ccos_, g_ccos); SYM(na, g_na); SYM(nc, g_nc);
    SYM(ah, g_ah); SYM(al, g_al); SYM(ch_, g_ch); SYM(cl_, g_cl);
    SYM(aadjh, g_aadjh); SYM(aadjl, g_aadjl); SYM(cadjh, g_cadjh); SYM(cadjl, g_cadjl);
    SYM(w1ah, g_w1ah); SYM(w1al, g_w1al); SYM(w2ah, g_w2ah); SYM(w2al, g_w2al);
    SYM(w1ch, g_w1ch); SYM(w1cl, g_w1cl); SYM(w2ch, g_w2ch); SYM(w2cl, g_w2cl);
    SYM(t1h, g_t1h); SYM(t1l, g_t1l); SYM(t2h, g_t2h); SYM(t2l, g_t2l);
    SYM(t3h, g_t3h); SYM(t3l, g_t3l);
    SYM(ofah, g_ofah); SYM(ofal, g_ofal); SYM(ofch, g_ofch); SYM(ofcl, g_ofcl);
    SYM(wp1h, g_wp1h); SYM(wp1l, g_wp1l); SYM(wp2h, g_wp2h); SYM(wp2l, g_wp2l);
    SYM(hp1, g_hp1); SYM(hp2, g_hp2); SYM(kp, g_kp);

    // 0) split inputs + weights to bf16 hi/lo
    split_k<<<1024, 256>>>(act, ah, al, (size_t)BQ * PP * DDA / 4);
    split_k<<<2048, 256>>>(comp, ch_, cl_, (size_t)BQ * PP * DDC / 4);
    split_k<<<256, 256>>>(a_w1, w1ah, w1al, (size_t)DDA * HID / 4);
    split_k<<<256, 256>>>(a_w2, w2ah, w2al, (size_t)HID * DDA / 4);
    split_k<<<512, 256>>>(c_w1, w1ch, w1cl, (size_t)DDC * HID / 4);
    split_k<<<512, 256>>>(c_w2, w2ch, w2cl, (size_t)HID * DDC / 4);

    zero_k<<<64, 256>>>((uint4*)wp1h, (size_t)DDA * 128 * 2 / 16);
    zero_k<<<64, 256>>>((uint4*)wp1l, (size_t)DDA * 128 * 2 / 16);
    zero_k<<<128, 256>>>((uint4*)wp2h, (size_t)DDC * 128 * 2 / 16);
    zero_k<<<128, 256>>>((uint4*)wp2l, (size_t)DDC * 128 * 2 / 16);
    padsplit_k<<<128, 256>>>(fa_w, wp1h, wp1l, DDA, 21, 0);
    padsplit_k<<<256, 256>>>(fc_w, wp2h, wp2l, DDC, 20, 0);
    padsplit_k<<<512, 256>>>(fr_w, wp2h, wp2l, DDC, 40, 20);

    // 1) Gram matrices, symmetric (TM=1) + mirror
    gx(1, 1, ah, al, ah, al, acos_, 0, 0, PP, PP, DDA, 0, 1,
       (long)PP * DDA, (long)PP * DDA, (long)PP * PP, BQ, 0, 0, 0, PP, 0);
    gx(1, 1, ch_, cl_, ch_, cl_, ccos_, 0, 0, PP, PP, DDC, 0, 1,
       (long)PP * DDC, (long)PP * DDC, (long)PP * PP, BQ, 0, 0, 0, PP, 0);
    mirror_k<<<dim3(32, 32, BQ), 256>>>(acos_, ccos_);

    // 2) norms
    norms_k<<<(BQ * PP + 255) / 256, 256>>>(acos_, na);
    norms_k<<<(BQ * PP + 255) / 256, 256>>>(ccos_, nc);

    // 3) graph construction
    build_adj_k<<<BQ * PP / 4, 128>>>(iou, dis, acos_, ccos_, na, nc, props,
                                      aadjh, aadjl, cadjh, cadjl);

    // 4) Act GCN chain
    gx(0, 1, ah, al, w1ah, w1al, 0, t1h, t1l, BQ * PP, HID, DDA, 0, 0,
       0, 0, 0, 1, 0, 0, 0, HID, 0);
    gx(0, 1, aadjh, aadjl, t1h, t1l, 0, t2h, t2l, PP, HID, PP, 0, 0,
       (long)PP * PP, (long)PP * HID, (long)PP * HID, BQ, a_b1, 0, 0, HID, 1);
    gx(0, 2, t2h, t2l, w2ah, w2al, 0, t3h, t3l, BQ * PP, DDA, HID, 0, 0,
       0, 0, 0, 1, 0, 0, 0, DDA, 0);
    gx(0, 2, aadjh, aadjl, t3h, t3l, 0, ofah, ofal, PP, DDA, PP, 0, 0,
       (long)PP * PP, (long)PP * DDA, (long)PP * DDA, BQ,
       a_b2, act, (long)PP * DDA, DDA, 0);
    // act head: 4 K-slices of 256
    gx(0, 1, ofah, ofal, wp1h, wp1l, hp1, 0, 0, BQ * PP, 128, DDA, 256, 0,
       0, 0, (long)BQ * PP * 128, 1, 0, 0, 0, 128, 0);

    // 5) Comp GCN chain
    // x@w1 comp: TM2 + K-split 2x1536 -> fp32 partials -> reduce+split to t1
    gx(0, 2, ch_, cl_, w1ch, w1cl, kp, 0, 0, BQ * PP, HID, DDC, 1536, 0,
       0, 0, (long)BQ * PP * HID, 1, 0, 0, 0, HID, 0);
    redsplit_k<<<2048, 256>>>(kp, (size_t)BQ * PP * HID / 4, 2, t1h, t1l,
                              (size_t)BQ * PP * HID / 4);
    gx(0, 1, cadjh, cadjl, t1h, t1l, 0, t2h, t2l, PP, HID, PP, 0, 0,
       (long)PP * PP, (long)PP * HID, (long)PP * HID, BQ, c_b1, 0, 0, HID, 1);
    gx(0, 2, t2h, t2l, w2ch, w2cl, 0, t3h, t3l, BQ * PP, DDC, HID, 0, 0,
       0, 0, 0, 1, 0, 0, 0, DDC, 0);
    gx(0, 2, cadjh, cadjl, t3h, t3l, 0, ofch, ofcl, PP, DDC, PP, 0, 0,
       (long)PP * PP, (long)PP * DDC, (long)PP * DDC, BQ,
       c_b2, comp, (long)PP * DDC, DDC, 0);
    // comp head: 8 K-slices of 384 (TM2)
    gx(0, 2, ofch, ofcl, wp2h, wp2l, hp2, 0, 0, BQ * PP, 128, DDC, 384, 0,
       0, 0, (long)BQ * PP * 128, 1, 0, 0, 0, 128, 0);

    // 6) head reduction -> out
    redheads_k<<<(BQ * PP * 81 + 255) / 256, 256>>>(hp1, hp2, fa_b, fc_b, fr_b, out);
}

// round 8
// speedup vs baseline: 1.0398x; 1.0136x over previous
#include <cuda_runtime.h>
#include <cuda_bf16.h>
#include <math.h>
#include <stdint.h>

#define BQ 4
#define PP 1024
#define DDA 1024
#define DDC 3072
#define HID 512
typedef __nv_bfloat16 bf16;

// ---------------- scratch (static device memory, no allocation) ----------------
__device__ float g_acos[(size_t)BQ*PP*PP];
__device__ float g_ccos[(size_t)BQ*PP*PP];
__device__ float g_na[BQ*PP];
__device__ float g_nc[BQ*PP];
__device__ bf16 g_ah[(size_t)BQ*PP*DDA], g_al[(size_t)BQ*PP*DDA];
__device__ bf16 g_ch[(size_t)BQ*PP*DDC], g_cl[(size_t)BQ*PP*DDC];
__device__ bf16 g_aadjh[(size_t)BQ*PP*PP], g_aadjl[(size_t)BQ*PP*PP];
__device__ bf16 g_cadjh[(size_t)BQ*PP*PP], g_cadjl[(size_t)BQ*PP*PP];
__device__ bf16 g_w1ah[DDA*HID], g_w1al[DDA*HID];
__device__ bf16 g_w2ah[HID*DDA], g_w2al[HID*DDA];
__device__ bf16 g_w1ch[DDC*HID], g_w1cl[DDC*HID];
__device__ bf16 g_w2ch[HID*DDC], g_w2cl[HID*DDC];
__device__ bf16 g_t1h[(size_t)BQ*PP*HID], g_t1l[(size_t)BQ*PP*HID];
__device__ bf16 g_t2h[(size_t)BQ*PP*HID], g_t2l[(size_t)BQ*PP*HID];
__device__ bf16 g_t3h[(size_t)BQ*PP*DDC], g_t3l[(size_t)BQ*PP*DDC];
__device__ bf16 g_ofah[(size_t)BQ*PP*DDA], g_ofal[(size_t)BQ*PP*DDA];
__device__ bf16 g_ofch[(size_t)BQ*PP*DDC], g_ofcl[(size_t)BQ*PP*DDC];
__device__ bf16 g_wp1h[DDA*128], g_wp1l[DDA*128];
__device__ bf16 g_wp2h[DDC*128], g_wp2l[DDC*128];
__device__ float g_hp1[(size_t)8*BQ*PP*128];
__device__ float g_hp2[(size_t)8*BQ*PP*128];
__device__ float g_kp[(size_t)2*BQ*PP*HID];

// ====================== low-level helpers ======================
__device__ __forceinline__ uint32_t smem_u32(const void* p) {
    uint32_t a;
    asm("{ .reg .u64 t; cvta.to.shared.u64 t, %1; cvt.u32.u64 %0, t; }" : "=r"(a) : "l"(p));
    return a;
}
__device__ __forceinline__ uint32_t pack_bf16x2(float lo_e, float hi_e) {
    uint32_t r;
    asm("cvt.rn.bf16x2.f32 %0, %1, %2;" : "=r"(r) : "f"(hi_e), "f"(lo_e));
    return r;
}
__device__ __forceinline__ void split2(float x, float y, uint32_t& h, uint32_t& l) {
    uint32_t ux = __float_as_uint(x), uy = __float_as_uint(y);
    h = __byte_perm(ux, uy, 0x7632);
    float lx = x - __uint_as_float(ux & 0xFFFF0000u);
    float ly = y - __uint_as_float(uy & 0xFFFF0000u);
    l = pack_bf16x2(lx, ly);
}
__device__ __forceinline__ void ldmx4(uint32_t* r, uint32_t addr) {
    asm volatile("ldmatrix.sync.aligned.m8n8.x4.shared.b16 {%0,%1,%2,%3}, [%4];"
                 : "=r"(r[0]), "=r"(r[1]), "=r"(r[2]), "=r"(r[3]) : "r"(addr));
}
__device__ __forceinline__ void ldmx4t(uint32_t* r, uint32_t addr) {
    asm volatile("ldmatrix.sync.aligned.m8n8.x4.trans.shared.b16 {%0,%1,%2,%3}, [%4];"
                 : "=r"(r[0]), "=r"(r[1]), "=r"(r[2]), "=r"(r[3]) : "r"(addr));
}
__device__ __forceinline__ void mma_bf16(float* c, const uint32_t* a, const uint32_t* b) {
    asm volatile(
        "mma.sync.aligned.m16n8k16.row.col.f32.bf16.bf16.f32 "
        "{%0,%1,%2,%3}, {%4,%5,%6,%7}, {%8,%9}, {%0,%1,%2,%3};"
        : "+f"(c[0]), "+f"(c[1]), "+f"(c[2]), "+f"(c[3])
        : "r"(a[0]), "r"(a[1]), "r"(a[2]), "r"(a[3]), "r"(b[0]), "r"(b[1]));
}
__device__ __forceinline__ void cp16(uint32_t dst, const void* src) {
    asm volatile("cp.async.cg.shared.global [%0], [%1], 16;" :: "r"(dst), "l"(src) : "memory");
}
#define CP_COMMIT() asm volatile("cp.async.commit_group;" ::: "memory")

// K-major tile swizzle: 64B rows, unit c in 0..3 -> c ^ ((row>>1)&3).
// Conflict-free per ldmatrix phase: even rows banks {0,4,8,12}, odd {16,20,24,28}.
__device__ __forceinline__ uint32_t ksw(int row, int c) {
    return (uint32_t)(row * 64) + ((uint32_t)(c ^ ((row >> 1) & 3)) << 4);
}

// ====================== bf16x3 multistage mma GEMM ======================
// CTA 128x128, 8 warps (2x4, 64x32 warp tile), 3 stages, 2 CTAs/SM.
// TBK=1: B hi/lo [N,K]. TBK=0: B hi/lo [K,N].
// symm: skip blocks bx<by. Klen>0: K-split (batch=1): blockIdx.x = kslice*nxt+ntile,
// fp32 partial at C + kslice*sC.
#define ATILE 8192
#define ASTG  16384
#define SBYTES 32768
#define NSTAGE 3
#define GSMEM (NSTAGE*SBYTES)

template<int TBK>
__global__ __launch_bounds__(256, 2)
void gemmx_k(const bf16* __restrict__ Ah, const bf16* __restrict__ Al,
             const bf16* __restrict__ Bh, const bf16* __restrict__ Bl,
             float* __restrict__ C, bf16* __restrict__ Ch, bf16* __restrict__ Cl,
             int N, int K, int Klen, int symm,
             long sA, long sB, long sC,
             const float* __restrict__ bias,
             const float* __restrict__ resid, long sR,
             int ldc, int relu_flag)
{
    if (!Klen && symm && blockIdx.x < blockIdx.y) return;
    extern __shared__ char sm[];
    uint32_t smb = smem_u32(sm);

    const int tid = threadIdx.x;
    const int lane = tid & 31;
    const int wid = tid >> 5;
    const int wm = (wid >> 2) * 64;
    const int wn = (wid & 3) * 32;

    long bz = blockIdx.z;
    const int bm = blockIdx.y * 128;
    const int nxt = N >> 7;
    int bn, kbase, kslice = 0;
    if (Klen) {
        kslice = (int)blockIdx.x / nxt;
        bn = ((int)blockIdx.x - kslice * nxt) << 7;
        kbase = kslice * Klen;
    } else {
        bn = (int)blockIdx.x << 7;
        kbase = 0;
    }
    const int KL = Klen ? Klen : K;

    const bf16* Ahb = Ah + bz * sA + (size_t)bm * K + kbase;
    const bf16* Alb = Al + bz * sA + (size_t)bm * K + kbase;
    const bf16* Bhb = TBK ? (Bh + bz * sB + (size_t)bn * K + kbase)
                          : (Bh + bz * sB + (size_t)kbase * N + bn);
    const bf16* Blb = TBK ? (Bl + bz * sB + (size_t)bn * K + kbase)
                          : (Bl + bz * sB + (size_t)kbase * N + bn);
    float* Cb = C ? (Klen ? C + (size_t)kslice * sC : C + bz * sC) : (float*)0;
    bf16* Chb = Ch ? Ch + bz * sC : (bf16*)0;
    bf16* Clb = Cl ? Cl + bz * sC : (bf16*)0;
    const float* Rb = resid ? resid + bz * sR : (const float*)0;

    float acc[4][4][4];
#pragma unroll
    for (int i = 0; i < 4; i++)
#pragma unroll
        for (int j = 0; j < 4; j++)
#pragma unroll
            for (int r = 0; r < 4; r++) acc[i][j][r] = 0.f;

    const int nch = KL >> 5;

    auto load_stage = [&](int kt, int s) {
        uint32_t base = smb + (uint32_t)s * SBYTES;
        int k0 = kt << 5;
#pragma unroll
        for (int it = 0; it < 4; it++) {
            int id = it * 256 + tid;
            int hl = id >> 9, rid = id & 511;
            int row = rid >> 2, c = rid & 3;
            cp16(base + hl * ATILE + ksw(row, c),
                 (hl ? Alb : Ahb) + (size_t)row * K + k0 + c * 8);
        }
        if (TBK) {
#pragma unroll
            for (int it = 0; it < 4; it++) {
                int id = it * 256 + tid;
                int hl = id >> 9, rid = id & 511;
                int row = rid >> 2, c = rid & 3;
                cp16(base + ASTG + hl * ATILE + ksw(row, c),
                     (hl ? Blb : Bhb) + (size_t)row * K + k0 + c * 8);
            }
        } else {
#pragma unroll
            for (int it = 0; it < 4; it++) {
                int id = it * 256 + tid;
                int hl = id >> 9, rid = id & 511;
                int k = rid >> 4, c = rid & 15;
                cp16(base + ASTG + hl * ATILE + k * 256 + ((c ^ (k & 7)) << 4),
                     (hl ? Blb : Bhb) + (size_t)(k0 + k) * N + c * 8);
            }
        }
        CP_COMMIT();
    };

    load_stage(0, 0);
    load_stage(1, 1);

    int sc = 0, sl = 2;
    for (int kt = 0; kt < nch; kt++) {
        asm volatile("cp.async.wait_group 1;" ::: "memory");
        __syncthreads();
        if (kt + 2 < nch) {
            load_stage(kt + 2, sl);
            sl = (sl + 1 == NSTAGE) ? 0 : sl + 1;
        } else {
            CP_COMMIT();
        }
        uint32_t aB = smb + (uint32_t)sc * SBYTES;
        uint32_t bB = aB + ASTG;
        sc = (sc + 1 == NSTAGE) ? 0 : sc + 1;

#pragma unroll
        for (int kh = 0; kh < 2; kh++) {
            uint32_t ahi[4][4], alo[4][4];
            {
                int u = kh * 2 + (lane >> 4);
#pragma unroll
                for (int i = 0; i < 4; i++) {
                    int r = wm + (lane & 15) + i * 16;
                    uint32_t ro = ksw(r, u);
                    ldmx4(ahi[i], aB + ro);
                    ldmx4(alo[i], aB + ATILE + ro);
                }
            }
#pragma unroll
            for (int jp = 0; jp < 2; jp++) {
                uint32_t bh2[4], bl2[4];
                if (TBK) {
                    int row = wn + jp * 16 + ((lane >> 4) << 3) + (lane & 7);
                    int u = kh * 2 + ((lane >> 3) & 1);
                    uint32_t ro = ksw(row, u);
                    ldmx4(bh2, bB + ro);
                    ldmx4(bl2, bB + ATILE + ro);
                } else {
                    int k = kh * 16 + ((lane >> 3) & 1) * 8 + (lane & 7);
                    uint32_t kro = (uint32_t)k << 8;
                    int colblk = (wn >> 3) + 2 * jp + (lane >> 4);
                    uint32_t ad = kro + ((uint32_t)(colblk ^ (k & 7)) << 4);
                    ldmx4t(bh2, bB + ad);
                    ldmx4t(bl2, bB + ATILE + ad);
                }
                int j0 = 2 * jp, j1 = 2 * jp + 1;
#pragma unroll
                for (int i = 0; i < 4; i++) {
                    mma_bf16(acc[i][j0], ahi[i], bh2 + 0);
                    mma_bf16(acc[i][j1], ahi[i], bh2 + 2);
                }
#pragma unroll
                for (int i = 0; i < 4; i++) {
                    mma_bf16(acc[i][j0], ahi[i], bl2 + 0);
                    mma_bf16(acc[i][j1], ahi[i], bl2 + 2);
                }
#pragma unroll
                for (int i = 0; i < 4; i++) {
                    mma_bf16(acc[i][j0], alo[i], bh2 + 0);
                    mma_bf16(acc[i][j1], alo[i], bh2 + 2);
                }
            }
        }
    }

    // ---- epilogue ----
#pragma unroll
    for (int i = 0; i < 4; i++) {
        int r0 = bm + wm + i * 16 + (lane >> 2);
        int r1 = r0 + 8;
#pragma unroll
        for (int j = 0; j < 4; j++) {
            int gc = bn + wn + j * 8 + (lane & 3) * 2;
            float2 v0 = make_float2(acc[i][j][0], acc[i][j][1]);
            float2 v1 = make_float2(acc[i][j][2], acc[i][j][3]);
            if (bias) {
                float2 bv = *reinterpret_cast<const float2*>(bias + gc);
                v0.x += bv.x; v0.y += bv.y;
                v1.x += bv.x; v1.y += bv.y;
            }
            if (Rb) {
                float2 q0 = *reinterpret_cast<const float2*>(Rb + (size_t)r0 * ldc + gc);
                float2 q1 = *reinterpret_cast<const float2*>(Rb + (size_t)r1 * ldc + gc);
                v0.x += q0.x; v0.y += q0.y;
                v1.x += q1.x; v1.y += q1.y;
            }
            if (relu_flag) {
                v0.x = fmaxf(v0.x, 0.f); v0.y = fmaxf(v0.y, 0.f);
                v1.x = fmaxf(v1.x, 0.f); v1.y = fmaxf(v1.y, 0.f);
            }
            if (Cb) {
                *reinterpret_cast<float2*>(Cb + (size_t)r0 * ldc + gc) = v0;
                *reinterpret_cast<float2*>(Cb + (size_t)r1 * ldc + gc) = v1;
            }
            if (Chb) {
                uint32_t h0, l0, h1, l1;
                split2(v0.x, v0.y, h0, l0);
                split2(v1.x, v1.y, h1, l1);
                *reinterpret_cast<uint32_t*>(Chb + (size_t)r0 * ldc + gc) = h0;
                *reinterpret_cast<uint32_t*>(Clb + (size_t)r0 * ldc + gc) = l0;
                *reinterpret_cast<uint32_t*>(Chb + (size_t)r1 * ldc + gc) = h1;
                *reinterpret_cast<uint32_t*>(Clb + (size_t)r1 * ldc + gc) = l1;
            }
        }
    }
}

// ====================== elementwise kernels ======================
__global__ void split_k(const float* __restrict__ s, bf16* __restrict__ h,
                        bf16* __restrict__ l, size_t n4)
{
    for (size_t i = (size_t)blockIdx.x * blockDim.x + threadIdx.x; i < n4;
         i += (size_t)gridDim.x * blockDim.x) {
        float4 v = reinterpret_cast<const float4*>(s)[i];
        uint32_t h0, l0, h1, l1;
        split2(v.x, v.y, h0, l0);
        split2(v.z, v.w, h1, l1);
        reinterpret_cast<uint2*>(h)[i] = make_uint2(h0, h1);
        reinterpret_cast<uint2*>(l)[i] = make_uint2(l0, l1);
    }
}

__global__ void redsplit_k(const float* __restrict__ p, size_t sstride4, int nsl,
                           bf16* __restrict__ h, bf16* __restrict__ l, size_t n4)
{
    for (size_t i = (size_t)blockIdx.x * blockDim.x + threadIdx.x; i < n4;
         i += (size_t)gridDim.x * blockDim.x) {
        float4 v = reinterpret_cast<const float4*>(p)[i];
        for (int s = 1; s < nsl; s++) {
            float4 w = reinterpret_cast<const float4*>(p)[s * sstride4 + i];
            v.x += w.x; v.y += w.y; v.z += w.z; v.w += w.w;
        }
        uint32_t h0, l0, h1, l1;
        split2(v.x, v.y, h0, l0);
        split2(v.z, v.w, h1, l1);
        reinterpret_cast<uint2*>(h)[i] = make_uint2(h0, h1);
        reinterpret_cast<uint2*>(l)[i] = make_uint2(l0, l1);
    }
}

__global__ void zero_k(uint4* __restrict__ p, size_t n16)
{
    for (size_t i = (size_t)blockIdx.x * blockDim.x + threadIdx.x; i < n16;
         i += (size_t)gridDim.x * blockDim.x)
        p[i] = make_uint4(0, 0, 0, 0);
}

__global__ void padsplit_k(const float* __restrict__ src, bf16* __restrict__ h,
                           bf16* __restrict__ l, int K, int Nsrc, int col0)
{
    int total = K * Nsrc;
    for (int i = blockIdx.x * blockDim.x + threadIdx.x; i < total;
         i += gridDim.x * blockDim.x) {
        int k = i / Nsrc, n = i - k * Nsrc;
        float v = src[i];
        uint32_t u = __float_as_uint(v);
        float lv = v - __uint_as_float(u & 0xFFFF0000u);
        size_t d = (size_t)k * 128 + col0 + n;
        reinterpret_cast<unsigned short*>(h)[d] = (unsigned short)(u >> 16);
        reinterpret_cast<unsigned short*>(l)[d] = (unsigned short)(pack_bf16x2(lv, lv) & 0xFFFFu);
    }
}

__global__ void norms_k(const float* __restrict__ G, float* __restrict__ nrm)
{
    int i = blockIdx.x * blockDim.x + threadIdx.x;
    if (i < BQ * PP) {
        int b = i >> 10, p = i & (PP - 1);
        nrm[i] = sqrtf(G[((size_t)b * PP + p) * PP + p]);
    }
}

__global__ __launch_bounds__(256)
void mirror_k(float* __restrict__ A, float* __restrict__ B)
{
    int tj = blockIdx.x, ti = blockIdx.y, b = blockIdx.z;
    if (ti <= tj || (ti >> 2) == (tj >> 2)) return;
    __shared__ float ta[32][33], tb[32][33];
    int tx = threadIdx.x & 31, ty = threadIdx.x >> 5;
    size_t base = (size_t)b * PP * PP;
#pragma unroll
    for (int it = 0; it < 4; it++) {
        int r = ty + it * 8;
        size_t src = base + (size_t)(tj * 32 + r) * PP + ti * 32 + tx;
        ta[r][tx] = A[src];
        tb[r][tx] = B[src];
    }
    __syncthreads();
#pragma unroll
    for (int it = 0; it < 4; it++) {
        int r = ty + it * 8;
        size_t dst = base + (size_t)(ti * 32 + r) * PP + tj * 32 + tx;
        A[dst] = ta[tx][r];
        B[dst] = tb[tx][r];
    }
}

__global__ void redheads_k(const float* __restrict__ hp1, const float* __restrict__ hp2,
                           const float* __restrict__ fab, const float* __restrict__ fcb,
                           const float* __restrict__ frb, float* __restrict__ out)
{
    int i = blockIdx.x * blockDim.x + threadIdx.x;
    int total = BQ * PP * 81;
    if (i >= total) return;
    int row = i / 81, col = i - row * 81;
    float v;
    if (col < 21) {
        v = fab[col];
#pragma unroll
        for (int s = 0; s < 8; s++)
            v += hp1[((size_t)s * BQ * PP + row) * 128 + col];
    } else {
        int c2 = col - 21;
        v = (c2 < 20) ? fcb[c2] : frb[c2 - 20];
#pragma unroll
        for (int s = 0; s < 8; s++)
            v += hp2[((size_t)s * BQ * PP + row) * 128 + c2];
    }
    out[i] = v;
}

// ---------------- graph construction ----------------
__device__ __forceinline__ void warp_argmin(float& v, int& l)
{
#pragma unroll
    for (int off = 16; off; off >>= 1) {
        float ov = __shfl_down_sync(0xffffffffu, v, off);
        int ol = __shfl_down_sync(0xffffffffu, l, off);
        if (ov < v) { v = ov; l = ol; }
    }
    v = __shfl_sync(0xffffffffu, v, 0);
    l = __shfl_sync(0xffffffffu, l, 0);
}
__device__ __forceinline__ void warp_argmax(float& v, int& l)
{
#pragma unroll
    for (int off = 16; off; off >>= 1) {
        float ov = __shfl_down_sync(0xffffffffu, v, off);
        int ol = __shfl_down_sync(0xffffffffu, l, off);
        if (ov > v) { v = ov; l = ol; }
    }
    v = __shfl_sync(0xffffffffu, v, 0);
    l = __shfl_sync(0xffffffffu, l, 0);
}

__global__ __launch_bounds__(128)
void build_adj_k(const float* __restrict__ iou, const float* __restrict__ dis,
                 const float* __restrict__ acos_, const float* __restrict__ ccos_,
                 const float* __restrict__ na, const float* __restrict__ nc,
                 const int* __restrict__ props,
                 bf16* __restrict__ awh, bf16* __restrict__ awl,
                 bf16* __restrict__ cwh, bf16* __restrict__ cwl)
{
    __shared__ float sio[4][PP];
    int warp = threadIdx.x >> 5, lane = threadIdx.x & 31;
    int row = blockIdx.x * 4 + warp;
    if (row >= BQ * PP) return;
    int b = row >> 10;
    int p = row & (PP - 1);
    const float* iour = iou + (size_t)row * PP;
    const float* disr = dis + (size_t)row * PP;
    const float* ar = acos_ + (size_t)row * PP;
    const float* cr = ccos_ + (size_t)row * PP;
    const float* nab = na + (b << 10);
    const float* ncb = nc + (b << 10);
    float npa = nab[p], npc = ncb[p];
    int pn = props[b];
    bool pv = p < pn;

    float* io_s = sio[warp];
    for (int q = lane; q < PP; q += 32) io_s[q] = iour[q];
    __syncwarp();

    float dv[6]; int di[6];
#pragma unroll
    for (int j = 0; j < 6; j++) { dv[j] = 3.0e38f; di[j] = -1; }
    float sv[2] = {-3.0e38f, -3.0e38f};
    int si[2] = {-1, -1};

    for (int q = lane; q < PP; q += 32) {
        float io = io_s[q];
        bool ip = io > 0.0f;
        bool qv = q < pn;
        bool v2 = pv && qv;

        float dm = v2 ? (ip ? 2.0f : disr[q]) : 1.0e9f;
        if (dm < dv[5]) {
            dv[5] = dm; di[5] = q;
#pragma unroll
            for (int j = 5; j > 0; j--) {
                if (dv[j] < dv[j - 1]) {
                    float tv = dv[j]; dv[j] = dv[j - 1]; dv[j - 1] = tv;
                    int ti = di[j]; di[j] = di[j - 1]; di[j - 1] = ti;
                }
            }
        }
        float av = ar[q] / (npa * nab[q] + 1e-6f);
        float sm = v2 ? (ip ? 0.0f : (av - (q == p ? 1.0f : 0.0f))) : -1.0e9f;
        if (sm > sv[1]) {
            if (sm > sv[0]) { sv[1] = sv[0]; si[1] = si[0]; sv[0] = sm; si[0] = q; }
            else            { sv[1] = sm; si[1] = q; }
        }
    }

    int sel[8];
    {
        int ptr = 0;
        for (int k = 0; k < 6; k++) {
            float cv = (ptr < 6) ? dv[ptr] : 3.0e38f;
            int ci = (ptr < 6) ? di[ptr] : -1;
            float v = cv; int l = lane;
            warp_argmin(v, l);
            sel[k] = __shfl_sync(0xffffffffu, ci, l);
            if (lane == l) ptr++;
        }
    }
    {
        int ptr = 0;
        for (int k = 0; k < 2; k++) {
            float cv = (ptr < 2) ? sv[ptr] : -3.0e38f;
            int ci = (ptr < 2) ? si[ptr] : -1;
            float v = cv; int l = lane;
            warp_argmax(v, l);
            sel[6 + k] = __shfl_sync(0xffffffffu, ci, l);
            if (lane == l) ptr++;
        }
    }
#pragma unroll
    for (int k = 0; k < 8; k++) {
        int q = sel[k];
        bool ok = (q >= 0) && pv && (q < pn) && !(io_s[q] > 0.0f);
        sel[k] = ok ? q : -1;
    }

    unsigned mbits = 0;
    for (int i = 0; i < 32; i++) {
        int q = lane + 32 * i;
        float io = io_s[q];
        bool bit = (q != p) && (io > 0.7f);
#pragma unroll
        for (int k = 0; k < 8; k++) bit |= (sel[k] == q);
        mbits |= (bit ? 1u : 0u) << i;
    }
    int cnt = __popc(mbits);
#pragma unroll
    for (int off = 16; off; off >>= 1) cnt += __shfl_xor_sync(0xffffffffu, cnt, off);
    float inv = 1.0f / ((float)cnt + 1e-6f);

    unsigned short* ah_ = reinterpret_cast<unsigned short*>(awh) + (size_t)row * PP;
    unsigned short* al_ = reinterpret_cast<unsigned short*>(awl) + (size_t)row * PP;
    unsigned short* ch_ = reinterpret_cast<unsigned short*>(cwh) + (size_t)row * PP;
    unsigned short* cl_ = reinterpret_cast<unsigned short*>(cwl) + (size_t)row * PP;
    for (int i = 0; i < 32; i++) {
        int q = lane + 32 * i;
        float m = ((mbits >> i) & 1u) ? inv : 0.0f;
        if (q == p) m += 1.0f;
        float av = ar[q] / (npa * nab[q] + 1e-6f);
        float cv = cr[q] / (npc * ncb[q] + 1e-6f);
        float a = fmaxf(av * m, 0.f);
        float c = fmaxf(cv * m, 0.f);
        uint32_t ua = __float_as_uint(a);
        uint32_t uc = __float_as_uint(c);
        float la = a - __uint_as_float(ua & 0xFFFF0000u);
        float lc = c - __uint_as_float(uc & 0xFFFF0000u);
        ah_[q] = (unsigned short)(ua >> 16);
        al_[q] = (unsigned short)(pack_bf16x2(la, la) & 0xFFFFu);
        ch_[q] = (unsigned short)(uc >> 16);
        cl_[q] = (unsigned short)(pack_bf16x2(lc, lc) & 0xFFFFu);
    }
}

// ---------------- host orchestration ----------------
static void gx(int tbk,
               const bf16* Ah, const bf16* Al, const bf16* Bh, const bf16* Bl,
               float* C, bf16* Ch, bf16* Cl,
               int M, int N, int K, int Klen, int symm,
               long sA, long sB, long sC, int batch,
               const float* bias, const float* resid, long sR,
               int ldc, int relu)
{
    int nxt = N >> 7;
    int gxd = Klen ? nxt * (K / Klen) : nxt;
    dim3 grid(gxd, M / 128, batch);
    if (tbk) {
        cudaFuncSetAttribute(gemmx_k<1>, cudaFuncAttributeMaxDynamicSharedMemorySize, GSMEM);
        gemmx_k<1><<<grid, 256, GSMEM>>>(Ah, Al, Bh, Bl, C, Ch, Cl, N, K, Klen, symm,
                                         sA, sB, sC, bias, resid, sR, ldc, relu);
    } else {
        cudaFuncSetAttribute(gemmx_k<0>, cudaFuncAttributeMaxDynamicSharedMemorySize, GSMEM);
        gemmx_k<0><<<grid, 256, GSMEM>>>(Ah, Al, Bh, Bl, C, Ch, Cl, N, K, Klen, symm,
                                         sA, sB, sC, bias, resid, sR, ldc, relu);
    }
}

#define SYM(var, sym) cudaGetSymbolAddress((void**)&var, sym)

extern "C" void kernel_launch(void* const* d_in, const int* in_sizes, int n_in,
                              void* d_out, int out_size)
{
    const float* act   = (const float*)d_in[0];
    const float* comp  = (const float*)d_in[1];
    const float* iou   = (const float*)d_in[2];
    const float* dis   = (const float*)d_in[3];
    const int*   props = (const int*)d_in[4];
    const float* a_w1  = (const float*)d_in[5];
    const float* a_b1  = (const float*)d_in[6];
    const float* a_w2  = (const float*)d_in[7];
    const float* a_b2  = (const float*)d_in[8];
    const float* c_w1  = (const float*)d_in[9];
    const float* c_b1  = (const float*)d_in[10];
    const float* c_w2  = (const float*)d_in[11];
    const float* c_b2  = (const float*)d_in[12];
    const float* fa_w  = (const float*)d_in[13];
    const float* fa_b  = (const float*)d_in[14];
    const float* fc_w  = (const float*)d_in[15];
    const float* fc_b  = (const float*)d_in[16];
    const float* fr_w  = (const float*)d_in[17];
    const float* fr_b  = (const float*)d_in[18];
    float* out = (float*)d_out;

    float *acos_, *ccos_, *na, *nc, *hp1, *hp2, *kp;
    bf16 *ah, *al, *ch_, *cl_, *aadjh, *aadjl, *cadjh, *cadjl;
    bf16 *w1ah, *w1al, *w2ah, *w2al, *w1ch, *w1cl, *w2ch, *w2cl;
    bf16 *t1h, *t1l, *t2h, *t2l, *t3h, *t3l, *ofah, *ofal, *ofch, *ofcl;
    bf16 *wp1h, *wp1l, *wp2h, *wp2l;
    SYM(acos_, g_acos); SYM(ccos_, g_ccos); SYM(na, g_na); SYM(nc, g_nc);
    SYM(ah, g_ah); SYM(al, g_al); SYM(ch_, g_ch); SYM(cl_, g_cl);
    SYM(aadjh, g_aadjh); SYM(aadjl, g_aadjl); SYM(cadjh, g_cadjh); SYM(cadjl, g_cadjl);
    SYM(w1ah, g_w1ah); SYM(w1al, g_w1al); SYM(w2ah, g_w2ah); SYM(w2al, g_w2al);
    SYM(w1ch, g_w1ch); SYM(w1cl, g_w1cl); SYM(w2ch, g_w2ch); SYM(w2cl, g_w2cl);
    SYM(t1h, g_t1h); SYM(t1l, g_t1l); SYM(t2h, g_t2h); SYM(t2l, g_t2l);
    SYM(t3h, g_t3h); SYM(t3l, g_t3l);
    SYM(ofah, g_ofah); SYM(ofal, g_ofal); SYM(ofch, g_ofch); SYM(ofcl, g_ofcl);
    SYM(wp1h, g_wp1h); SYM(wp1l, g_wp1l); SYM(wp2h, g_wp2h); SYM(wp2l, g_wp2l);
    SYM(hp1, g_hp1); SYM(hp2, g_hp2); SYM(kp, g_kp);

    // Launches 1-2: input splits (needed by grams)
    split_k<<<1024, 256>>>(act, ah, al, (size_t)BQ * PP * DDA / 4);
    split_k<<<2048, 256>>>(comp, ch_, cl_, (size_t)BQ * PP * DDC / 4);
    // Launches 3-4: act weight splits
    split_k<<<256, 256>>>(a_w1, w1ah, w1al, (size_t)DDA * HID / 4);
    split_k<<<256, 256>>>(a_w2, w2ah, w2al, (size_t)HID * DDA / 4);
    // Launch 5: gram act; Launch 6: gram comp (profiled by ncu -s 5 -c 1)
    gx(1, ah, al, ah, al, acos_, 0, 0, PP, PP, DDA, 0, 1,
       (long)PP * DDA, (long)PP * DDA, (long)PP * PP, BQ, 0, 0, 0, PP, 0);
    gx(1, ch_, cl_, ch_, cl_, ccos_, 0, 0, PP, PP, DDC, 0, 1,
       (long)PP * DDC, (long)PP * DDC, (long)PP * PP, BQ, 0, 0, 0, PP, 0);

    // remaining prep
    split_k<<<512, 256>>>(c_w1, w1ch, w1cl, (size_t)DDC * HID / 4);
    split_k<<<512, 256>>>(c_w2, w2ch, w2cl, (size_t)HID * DDC / 4);
    zero_k<<<64, 256>>>((uint4*)wp1h, (size_t)DDA * 128 * 2 / 16);
    zero_k<<<64, 256>>>((uint4*)wp1l, (size_t)DDA * 128 * 2 / 16);
    zero_k<<<128, 256>>>((uint4*)wp2h, (size_t)DDC * 128 * 2 / 16);
    zero_k<<<128, 256>>>((uint4*)wp2l, (size_t)DDC * 128 * 2 / 16);
    padsplit_k<<<128, 256>>>(fa_w, wp1h, wp1l, DDA, 21, 0);
    padsplit_k<<<256, 256>>>(fc_w, wp2h, wp2l, DDC, 20, 0);
    padsplit_k<<<512, 256>>>(fr_w, wp2h, wp2l, DDC, 40, 20);

    // norms read gram diagonal (computed in diagonal blocks, pre-mirror is fine)
    norms_k<<<(BQ * PP + 255) / 256, 256>>>(acos_, na);
    norms_k<<<(BQ * PP + 255) / 256, 256>>>(ccos_, nc);
    mirror_k<<<dim3(32, 32, BQ), 256>>>(acos_, ccos_);

    build_adj_k<<<BQ * PP / 4, 128>>>(iou, dis, acos_, ccos_, na, nc, props,
                                      aadjh, aadjl, cadjh, cadjl);

    // Act GCN chain
    // x@w1 act: K-split 2x512 (batch flattened) -> fp32 partials -> redsplit
    gx(0, ah, al, w1ah, w1al, kp, 0, 0, BQ * PP, HID, DDA, 512, 0,
       0, 0, (long)BQ * PP * HID, 1, 0, 0, 0, HID, 0);
    redsplit_k<<<2048, 256>>>(kp, (size_t)BQ * PP * HID / 4, 2, t1h, t1l,
                              (size_t)BQ * PP * HID / 4);
    gx(0, aadjh, aadjl, t1h, t1l, 0, t2h, t2l, PP, HID, PP, 0, 0,
       (long)PP * PP, (long)PP * HID, (long)PP * HID, BQ, a_b1, 0, 0, HID, 1);
    gx(0, t2h, t2l, w2ah, w2al, 0, t3h, t3l, BQ * PP, DDA, HID, 0, 0,
       0, 0, 0, 1, 0, 0, 0, DDA, 0);
    gx(0, aadjh, aadjl, t3h, t3l, 0, ofah, ofal, PP, DDA, PP, 0, 0,
       (long)PP * PP, (long)PP * DDA, (long)PP * DDA, BQ,
       a_b2, act, (long)PP * DDA, DDA, 0);
    // act head: 8 K-slices of 128
    gx(0, ofah, ofal, wp1h, wp1l, hp1, 0, 0, BQ * PP, 128, DDA, 128, 0,
       0, 0, (long)BQ * PP * 128, 1, 0, 0, 0, 128, 0);

    // Comp GCN chain
    gx(0, ch_, cl_, w1ch, w1cl, kp, 0, 0, BQ * PP, HID, DDC, 1536, 0,
       0, 0, (long)BQ * PP * HID, 1, 0, 0, 0, HID, 0);
    redsplit_k<<<2048, 256>>>(kp, (size_t)BQ * PP * HID / 4, 2, t1h, t1l,
                              (size_t)BQ * PP * HID / 4);
    gx(0, cadjh, cadjl, t1h, t1l, 0, t2h, t2l, PP, HID, PP, 0, 0,
       (long)PP * PP, (long)PP * HID, (long)PP * HID, BQ, c_b1, 0, 0, HID, 1);
    gx(0, t2h, t2l, w2ch, w2cl, 0, t3h, t3l, BQ * PP, DDC, HID, 0, 0,
       0, 0, 0, 1, 0, 0, 0, DDC, 0);
    gx(0, cadjh, cadjl, t3h, t3l, 0, ofch, ofcl, PP, DDC, PP, 0, 0,
       (long)PP * PP, (long)PP * DDC, (long)PP * DDC, BQ,
       c_b2, comp, (long)PP * DDC, DDC, 0);
    // comp head: 8 K-slices of 384
    gx(0, ofch, ofcl, wp2h, wp2l, hp2, 0, 0, BQ * PP, 128, DDC, 384, 0,
       0, 0, (long)BQ * PP * 128, 1, 0, 0, 0, 128, 0);

    // head reduction -> out
    redheads_k<<<(BQ * PP * 81 + 255) / 256, 256>>>(hp1, hp2, fa_b, fc_b, fr_b, out);
}